// round 2
// baseline (speedup 1.0000x reference)
#include <cuda_runtime.h>
#include <math.h>
#include <stdint.h>

#define CH 128
#define N_NODES_MAX 100000
#define N_EDGES_MAX 800000

// ---------------- scratch (static device globals; no runtime allocation) ----
__device__ float g_q[(size_t)N_NODES_MAX * CH];
__device__ float g_k[(size_t)N_NODES_MAX * CH];
__device__ float g_v[(size_t)N_NODES_MAX * CH];
__device__ float g_h[(size_t)N_NODES_MAX * CH];      // layer1 output / layer2 input
__device__ float g_escore[N_EDGES_MAX];
__device__ float g_eexp[N_EDGES_MAX];
__device__ unsigned g_segmax[N_NODES_MAX];           // monotone-encoded float max
__device__ float g_segsum[N_NODES_MAX];
__device__ int g_src[N_EDGES_MAX];
__device__ int g_dst[N_EDGES_MAX];
__device__ int g_is64;

// monotone float<->uint encoding so atomicMax(unsigned) == float max
__device__ __forceinline__ unsigned enc_f(float f) {
    unsigned u = __float_as_uint(f);
    return (u & 0x80000000u) ? ~u : (u | 0x80000000u);
}
__device__ __forceinline__ float dec_f(unsigned u) {
    return (u & 0x80000000u) ? __uint_as_float(u ^ 0x80000000u) : __uint_as_float(~u);
}

// ---------------- edge_index dtype detection + normalization ----------------
// int64 little-endian with values < 2^31 => every odd 32-bit word is 0.
__global__ void detect_kernel(const unsigned* __restrict__ raw) {
    __shared__ int cnt;
    if (threadIdx.x == 0) cnt = 0;
    __syncthreads();
    int zeros = 0;
    for (int i = 1 + 2 * (int)threadIdx.x; i < 4096; i += 2 * 256)
        if (raw[i] == 0u) zeros++;
    atomicAdd(&cnt, zeros);
    __syncthreads();
    if (threadIdx.x == 0) g_is64 = (cnt > 1024) ? 1 : 0;
}

__global__ void convert_edges_kernel(const void* __restrict__ raw, int E) {
    int i = blockIdx.x * blockDim.x + threadIdx.x;
    if (i >= E) return;
    if (g_is64) {
        const long long* p = (const long long*)raw;
        g_src[i] = (int)p[i];
        g_dst[i] = (int)p[(size_t)E + i];
    } else {
        const int* p = (const int*)raw;
        g_src[i] = p[i];
        g_dst[i] = p[E + i];
    }
}

__global__ void init_seg_kernel(int N) {
    int i = blockIdx.x * blockDim.x + threadIdx.x;
    if (i < N) { g_segmax[i] = 0u; g_segsum[i] = 0.0f; }
}

// ---------------- fp32 GEMM: C[M,128] = act(A)[M,128] @ W[128,128] + b ------
// 128x128 block tile, 256 threads, 8x8 microtile, BK=8.
template<bool RELU_IN>
__global__ __launch_bounds__(256, 2) void gemm_bias_kernel(
    const float* __restrict__ A, const float* __restrict__ W,
    const float* __restrict__ bias, float* __restrict__ Cout, int M)
{
    __shared__ float As[8][128];
    __shared__ float Bs[8][128];
    const int t = threadIdx.x;
    const int tx = t & 15;        // 0..15 -> output cols tx*8..+7
    const int ty = t >> 4;        // 0..15 -> output rows ty*8..+7
    const int row0 = blockIdx.x * 128;

    const int a_row = t >> 1;           // 0..127
    const int a_col = (t & 1) * 4;      // 0 or 4
    const int w_row = t >> 5;           // 0..7
    const int w_col = (t & 31) * 4;     // 0..124

    float acc[8][8];
#pragma unroll
    for (int i = 0; i < 8; i++)
#pragma unroll
        for (int j = 0; j < 8; j++) acc[i][j] = 0.0f;

    for (int k0 = 0; k0 < CH; k0 += 8) {
        int gr = row0 + a_row;
        float4 av = make_float4(0.f, 0.f, 0.f, 0.f);
        if (gr < M)
            av = *reinterpret_cast<const float4*>(A + (size_t)gr * CH + k0 + a_col);
        if (RELU_IN) {
            av.x = fmaxf(av.x, 0.f); av.y = fmaxf(av.y, 0.f);
            av.z = fmaxf(av.z, 0.f); av.w = fmaxf(av.w, 0.f);
        }
        As[a_col + 0][a_row] = av.x;
        As[a_col + 1][a_row] = av.y;
        As[a_col + 2][a_row] = av.z;
        As[a_col + 3][a_row] = av.w;

        float4 wv = *reinterpret_cast<const float4*>(W + (size_t)(k0 + w_row) * CH + w_col);
        *reinterpret_cast<float4*>(&Bs[w_row][w_col]) = wv;
        __syncthreads();

#pragma unroll
        for (int kk = 0; kk < 8; kk++) {
            float ar[8], br[8];
            *reinterpret_cast<float4*>(ar)     = *reinterpret_cast<float4*>(&As[kk][ty * 8]);
            *reinterpret_cast<float4*>(ar + 4) = *reinterpret_cast<float4*>(&As[kk][ty * 8 + 4]);
            *reinterpret_cast<float4*>(br)     = *reinterpret_cast<float4*>(&Bs[kk][tx * 8]);
            *reinterpret_cast<float4*>(br + 4) = *reinterpret_cast<float4*>(&Bs[kk][tx * 8 + 4]);
#pragma unroll
            for (int i = 0; i < 8; i++)
#pragma unroll
                for (int j = 0; j < 8; j++)
                    acc[i][j] += ar[i] * br[j];
        }
        __syncthreads();
    }

    float bv[8];
#pragma unroll
    for (int j = 0; j < 8; j++) bv[j] = bias[tx * 8 + j];

#pragma unroll
    for (int i = 0; i < 8; i++) {
        int gr = row0 + ty * 8 + i;
        if (gr < M) {
            float4 o0, o1;
            o0.x = acc[i][0] + bv[0]; o0.y = acc[i][1] + bv[1];
            o0.z = acc[i][2] + bv[2]; o0.w = acc[i][3] + bv[3];
            o1.x = acc[i][4] + bv[4]; o1.y = acc[i][5] + bv[5];
            o1.z = acc[i][6] + bv[6]; o1.w = acc[i][7] + bv[7];
            *reinterpret_cast<float4*>(Cout + (size_t)gr * CH + tx * 8)     = o0;
            *reinterpret_cast<float4*>(Cout + (size_t)gr * CH + tx * 8 + 4) = o1;
        }
    }
}

// ---------------- edge pass 1: score + segment max --------------------------
// one warp per edge; lane l handles channels 4l..4l+3
__global__ __launch_bounds__(256) void edge_score_kernel(int E) {
    int w = (blockIdx.x * blockDim.x + threadIdx.x) >> 5;
    if (w >= E) return;
    int lane = threadIdx.x & 31;
    int s = g_src[w], d = g_dst[w];
    float4 qv = *reinterpret_cast<const float4*>(g_q + (size_t)d * CH + lane * 4);
    float4 kv = *reinterpret_cast<const float4*>(g_k + (size_t)s * CH + lane * 4);
    float p = qv.x * kv.x + qv.y * kv.y + qv.z * kv.z + qv.w * kv.w;
#pragma unroll
    for (int o = 16; o > 0; o >>= 1) p += __shfl_down_sync(0xffffffffu, p, o);
    if (lane == 0) {
        float sc = p * 0.08838834764831845f;   // 1/sqrt(128)
        g_escore[w] = sc;
        atomicMax(&g_segmax[d], enc_f(sc));
    }
}

// ---------------- edge pass 2: exp + segment sum -----------------------------
__global__ __launch_bounds__(256) void edge_exp_kernel(int E) {
    int e = blockIdx.x * blockDim.x + threadIdx.x;
    if (e >= E) return;
    int d = g_dst[e];
    float m = dec_f(g_segmax[d]);
    float ex = expf(g_escore[e] - m);
    g_eexp[e] = ex;
    atomicAdd(&g_segsum[d], ex);
}

// ---------------- edge pass 3: scatter alpha * v[src] into out ---------------
// one warp per edge; 16B vector reductions (4x fewer atomic ops than scalar)
__global__ __launch_bounds__(256) void edge_scatter_kernel(float* __restrict__ out, int E) {
    int w = (blockIdx.x * blockDim.x + threadIdx.x) >> 5;
    if (w >= E) return;
    int lane = threadIdx.x & 31;
    int s = g_src[w], d = g_dst[w];
    float alpha = g_eexp[w] / g_segsum[d];
    float4 vv = *reinterpret_cast<const float4*>(g_v + (size_t)s * CH + lane * 4);
    vv.x *= alpha; vv.y *= alpha; vv.z *= alpha; vv.w *= alpha;
    float* p = out + (size_t)d * CH + lane * 4;
    asm volatile("red.global.add.v4.f32 [%0], {%1, %2, %3, %4};"
                 :: "l"(p), "f"(vv.x), "f"(vv.y), "f"(vv.z), "f"(vv.w)
                 : "memory");
}

// ---------------- host ------------------------------------------------------
extern "C" void kernel_launch(void* const* d_in, const int* in_sizes, int n_in,
                              void* d_out, int out_size)
{
    const float* x    = (const float*)d_in[0];
    const void*  eidx = d_in[1];
    const float* Wq1 = (const float*)d_in[2];  const float* bq1 = (const float*)d_in[3];
    const float* Wk1 = (const float*)d_in[4];  const float* bk1 = (const float*)d_in[5];
    const float* Wv1 = (const float*)d_in[6];  const float* bv1 = (const float*)d_in[7];
    const float* Ws1 = (const float*)d_in[8];  const float* bs1 = (const float*)d_in[9];
    const float* Wq2 = (const float*)d_in[10]; const float* bq2 = (const float*)d_in[11];
    const float* Wk2 = (const float*)d_in[12]; const float* bk2 = (const float*)d_in[13];
    const float* Wv2 = (const float*)d_in[14]; const float* bv2 = (const float*)d_in[15];
    const float* Ws2 = (const float*)d_in[16]; const float* bs2 = (const float*)d_in[17];

    const int N = in_sizes[0] / CH;
    const int E = in_sizes[1] / 2;

    float *q, *k, *v, *h;
    cudaGetSymbolAddress((void**)&q, g_q);
    cudaGetSymbolAddress((void**)&k, g_k);
    cudaGetSymbolAddress((void**)&v, g_v);
    cudaGetSymbolAddress((void**)&h, g_h);
    float* out = (float*)d_out;

    const int nBlocksNode = (N + 255) / 256;
    const int nBlocksEdge = (E + 255) / 256;
    const int nBlocksEdgeWarp = (int)(((long long)E * 32 + 255) / 256);
    const int nBlocksGemm = (N + 127) / 128;

    // edge normalization (int64 vs int32 robust)
    detect_kernel<<<1, 256>>>((const unsigned*)eidx);
    convert_edges_kernel<<<nBlocksEdge, 256>>>(eidx, E);

    // ---------------- layer 1 ----------------
    init_seg_kernel<<<nBlocksNode, 256>>>(N);
    gemm_bias_kernel<false><<<nBlocksGemm, 256>>>(x, Wq1, bq1, q, N);
    gemm_bias_kernel<false><<<nBlocksGemm, 256>>>(x, Wk1, bk1, k, N);
    gemm_bias_kernel<false><<<nBlocksGemm, 256>>>(x, Wv1, bv1, v, N);
    gemm_bias_kernel<false><<<nBlocksGemm, 256>>>(x, Ws1, bs1, h, N);  // skip into accumulator
    edge_score_kernel<<<nBlocksEdgeWarp, 256>>>(E);
    edge_exp_kernel<<<nBlocksEdge, 256>>>(E);
    edge_scatter_kernel<<<nBlocksEdgeWarp, 256>>>(h, E);

    // ---------------- layer 2 (relu fused into GEMM A-loads) ----------------
    init_seg_kernel<<<nBlocksNode, 256>>>(N);
    gemm_bias_kernel<true><<<nBlocksGemm, 256>>>(h, Wq2, bq2, q, N);
    gemm_bias_kernel<true><<<nBlocksGemm, 256>>>(h, Wk2, bk2, k, N);
    gemm_bias_kernel<true><<<nBlocksGemm, 256>>>(h, Wv2, bv2, v, N);
    gemm_bias_kernel<true><<<nBlocksGemm, 256>>>(h, Ws2, bs2, out, N); // skip into d_out
    edge_score_kernel<<<nBlocksEdgeWarp, 256>>>(E);
    edge_exp_kernel<<<nBlocksEdge, 256>>>(E);
    edge_scatter_kernel<<<nBlocksEdgeWarp, 256>>>(out, E);
}

// round 5
// speedup vs baseline: 1.4517x; 1.4517x over previous
#include <cuda_runtime.h>
#include <cuda_bf16.h>
#include <math.h>
#include <stdint.h>

#define CH 128
#define N_NODES_MAX 100000
#define N_EDGES_MAX 800000
#define PITCH 136   // bf16 elems per smem row (128 + 8 pad -> conflict-free ldmatrix)

// ---------------- scratch (static device globals; no runtime allocation) ----
__device__ float g_q[(size_t)N_NODES_MAX * CH];
__device__ float g_k[(size_t)N_NODES_MAX * CH];
__device__ float g_v[(size_t)N_NODES_MAX * CH];
__device__ float g_h[(size_t)N_NODES_MAX * CH];
__device__ float g_escore[N_EDGES_MAX];
__device__ float g_eexp[N_EDGES_MAX];
__device__ unsigned g_segmax[N_NODES_MAX];
__device__ float g_segsum[N_NODES_MAX];
__device__ int g_src[N_EDGES_MAX];
__device__ int g_dst[N_EDGES_MAX];
__device__ int g_is64;
// pre-transposed, hi/lo-split weights: [8 matrices][n*128 + k] bf16  (B col-major)
__device__ __nv_bfloat16 g_wth[8][CH * CH];
__device__ __nv_bfloat16 g_wtl[8][CH * CH];

// ---------------- helpers ---------------------------------------------------
__device__ __forceinline__ uint32_t smem_u32(const void* p) {
    uint32_t a;
    asm("{ .reg .u64 t; cvta.to.shared.u64 t, %1; cvt.u32.u64 %0, t; }" : "=r"(a) : "l"(p));
    return a;
}
__device__ __forceinline__ void ldmatrix_x4(uint32_t* r, uint32_t addr) {
    asm volatile("ldmatrix.sync.aligned.m8n8.x4.shared.b16 {%0,%1,%2,%3}, [%4];"
                 : "=r"(r[0]), "=r"(r[1]), "=r"(r[2]), "=r"(r[3]) : "r"(addr));
}
__device__ __forceinline__ void mma_bf16(float* c, const uint32_t* a, const uint32_t* b) {
    asm volatile("mma.sync.aligned.m16n8k16.row.col.f32.bf16.bf16.f32 "
                 "{%0,%1,%2,%3}, {%4,%5,%6,%7}, {%8,%9}, {%0,%1,%2,%3};"
                 : "+f"(c[0]), "+f"(c[1]), "+f"(c[2]), "+f"(c[3])
                 : "r"(a[0]), "r"(a[1]), "r"(a[2]), "r"(a[3]), "r"(b[0]), "r"(b[1]));
}

__device__ __forceinline__ unsigned enc_f(float f) {
    unsigned u = __float_as_uint(f);
    return (u & 0x80000000u) ? ~u : (u | 0x80000000u);
}
__device__ __forceinline__ float dec_f(unsigned u) {
    return (u & 0x80000000u) ? __uint_as_float(u ^ 0x80000000u) : __uint_as_float(~u);
}

// ---------------- edge_index dtype detection + normalization ----------------
__global__ void detect_kernel(const unsigned* __restrict__ raw) {
    __shared__ int cnt;
    if (threadIdx.x == 0) cnt = 0;
    __syncthreads();
    int zeros = 0;
    for (int i = 1 + 2 * (int)threadIdx.x; i < 4096; i += 2 * 256)
        if (raw[i] == 0u) zeros++;
    atomicAdd(&cnt, zeros);
    __syncthreads();
    if (threadIdx.x == 0) g_is64 = (cnt > 1024) ? 1 : 0;
}

__global__ void convert_edges_kernel(const void* __restrict__ raw, int E) {
    int i = blockIdx.x * blockDim.x + threadIdx.x;
    if (i >= E) return;
    if (g_is64) {
        const long long* p = (const long long*)raw;
        g_src[i] = (int)p[i];
        g_dst[i] = (int)p[(size_t)E + i];
    } else {
        const int* p = (const int*)raw;
        g_src[i] = p[i];
        g_dst[i] = p[E + i];
    }
}

__global__ void init_seg_kernel(int N) {
    int i = blockIdx.x * blockDim.x + threadIdx.x;
    if (i < N) { g_segmax[i] = 0u; g_segsum[i] = 0.0f; }
}

// ---------------- weight prep: transpose + bf16 hi/lo split -----------------
__global__ void prep_w_kernel(const float* W0, const float* W1, const float* W2, const float* W3,
                              const float* W4, const float* W5, const float* W6, const float* W7) {
    const float* Ws[8] = {W0, W1, W2, W3, W4, W5, W6, W7};
    const float* W = Ws[blockIdx.x];
    int n = threadIdx.x;   // output column -> row of transposed tile
    for (int k = 0; k < CH; k++) {
        float w = W[k * CH + n];
        __nv_bfloat16 h = __float2bfloat16(w);
        float lo = w - __bfloat162float(h);
        g_wth[blockIdx.x][n * CH + k] = h;
        g_wtl[blockIdx.x][n * CH + k] = __float2bfloat16(lo);
    }
}

// ---------------- fused 4-GEMM layer kernel (mma.sync bf16, split-bf16) ------
// CTA: 128 rows x 128 cols x 4 weight matrices. 8 warps, warp tile 32x64.
// smem: A_hi[128][136], A_lo[128][136], Wbuf[128][136] (bf16)
#define SA_HI 0
#define SA_LO (128 * PITCH * 2)
#define SW_BUF (2 * 128 * PITCH * 2)
#define SM_TOTAL (3 * 128 * PITCH * 2)

template<bool RELU>
__global__ __launch_bounds__(256, 1) void gemm4_mma_kernel(
    const float* __restrict__ A, int wbase,
    const float* __restrict__ b0, const float* __restrict__ b1,
    const float* __restrict__ b2, const float* __restrict__ b3,
    float* __restrict__ o0, float* __restrict__ o1,
    float* __restrict__ o2, float* __restrict__ o3, int M)
{
    extern __shared__ char smem[];
    const uint32_t sb = smem_u32(smem);
    const int tid = threadIdx.x;
    const int lane = tid & 31;
    const int warp = tid >> 5;
    const int m0 = (warp >> 1) * 32;     // warp tile row base (0..96)
    const int n0 = (warp & 1) * 64;      // warp tile col base (0 or 64)
    const int row0 = blockIdx.x * 128;

    // ---- A tile: fp32 load -> hi/lo bf16 split into padded smem -------------
#pragma unroll
    for (int i = 0; i < 16; i++) {
        int idx = i * 256 + tid;             // 4096 float4s
        int row = idx >> 5, c4 = idx & 31;
        int gr = row0 + row;
        float4 xv = make_float4(0.f, 0.f, 0.f, 0.f);
        if (gr < M) xv = *reinterpret_cast<const float4*>(A + (size_t)gr * CH + c4 * 4);
        if (RELU) {
            xv.x = fmaxf(xv.x, 0.f); xv.y = fmaxf(xv.y, 0.f);
            xv.z = fmaxf(xv.z, 0.f); xv.w = fmaxf(xv.w, 0.f);
        }
        __nv_bfloat16 h0 = __float2bfloat16(xv.x), h1 = __float2bfloat16(xv.y);
        __nv_bfloat16 h2 = __float2bfloat16(xv.z), h3 = __float2bfloat16(xv.w);
        float l0 = xv.x - __bfloat162float(h0), l1 = xv.y - __bfloat162float(h1);
        float l2 = xv.z - __bfloat162float(h2), l3 = xv.w - __bfloat162float(h3);
        __nv_bfloat16 hs[4] = {h0, h1, h2, h3};
        __nv_bfloat16 ls[4] = {__float2bfloat16(l0), __float2bfloat16(l1),
                               __float2bfloat16(l2), __float2bfloat16(l3)};
        uint32_t off = (uint32_t)(row * PITCH + c4 * 4) * 2;
        *reinterpret_cast<uint2*>(smem + SA_HI + off) = *reinterpret_cast<uint2*>(hs);
        *reinterpret_cast<uint2*>(smem + SA_LO + off) = *reinterpret_cast<uint2*>(ls);
    }

    // per-lane ldmatrix address components
    const int a_row = (lane & 15);                    // + m_base
    const int a_col = (lane >> 4) << 3;               // + k
    const int b_nrow = (lane & 7) + ((lane & 16) ? 8 : 0);  // + n_base
    const int b_kcol = (lane & 8) ? 8 : 0;                  // + k

    const float* biases[4] = {b0, b1, b2, b3};
    float* outs[4] = {o0, o1, o2, o3};

    for (int j = 0; j < 4; j++) {
        float c[2][8][4];
#pragma unroll
        for (int i = 0; i < 2; i++)
#pragma unroll
            for (int tn = 0; tn < 8; tn++)
#pragma unroll
                for (int e = 0; e < 4; e++) c[i][tn][e] = 0.0f;

        // two passes: p=0 -> Whi (Ahi & Alo terms), p=1 -> Wlo (Ahi term)
#pragma unroll
        for (int p = 0; p < 2; p++) {
            const __nv_bfloat16* wsrc = p ? g_wtl[wbase + j] : g_wth[wbase + j];
            __syncthreads();   // protect Wbuf from readers of previous pass
#pragma unroll
            for (int i = 0; i < 8; i++) {
                int idx = i * 256 + tid;           // 2048 uint4
                int n = idx >> 4, k0 = (idx & 15) * 8;
                uint4 wv = *reinterpret_cast<const uint4*>(wsrc + n * CH + k0);
                *reinterpret_cast<uint4*>(smem + SW_BUF + (uint32_t)(n * PITCH + k0) * 2) = wv;
            }
            __syncthreads();

#pragma unroll
            for (int ks = 0; ks < 8; ks++) {
                const int k = ks * 16;
                // B frags: 4x ldmatrix.x4, each covers 2 n-tiles (n16 x k16)
                uint32_t bfr[8][2];
#pragma unroll
                for (int q = 0; q < 4; q++) {
                    uint32_t r[4];
                    uint32_t addr = sb + SW_BUF +
                        (uint32_t)((n0 + q * 16 + b_nrow) * PITCH + k + b_kcol) * 2;
                    ldmatrix_x4(r, addr);
                    bfr[q * 2 + 0][0] = r[0]; bfr[q * 2 + 0][1] = r[1];
                    bfr[q * 2 + 1][0] = r[2]; bfr[q * 2 + 1][1] = r[3];
                }
                // A hi frags (always needed)
                uint32_t ah[2][4];
#pragma unroll
                for (int i = 0; i < 2; i++) {
                    uint32_t addr = sb + SA_HI +
                        (uint32_t)((m0 + i * 16 + a_row) * PITCH + k + a_col) * 2;
                    ldmatrix_x4(ah[i], addr);
                }
#pragma unroll
                for (int i = 0; i < 2; i++)
#pragma unroll
                    for (int tn = 0; tn < 8; tn++)
                        mma_bf16(c[i][tn], ah[i], bfr[tn]);
                if (p == 0) {
                    uint32_t al[2][4];
#pragma unroll
                    for (int i = 0; i < 2; i++) {
                        uint32_t addr = sb + SA_LO +
                            (uint32_t)((m0 + i * 16 + a_row) * PITCH + k + a_col) * 2;
                        ldmatrix_x4(al[i], addr);
                    }
#pragma unroll
                    for (int i = 0; i < 2; i++)
#pragma unroll
                        for (int tn = 0; tn < 8; tn++)
                            mma_bf16(c[i][tn], al[i], bfr[tn]);
                }
            }
        }

        // ---- epilogue j: bias + store ---------------------------------------
        const float* bp = biases[j];
        float* op = outs[j];
#pragma unroll
        for (int i = 0; i < 2; i++) {
            int r0g = row0 + m0 + i * 16 + (lane >> 2);
            int r1g = r0g + 8;
#pragma unroll
            for (int tn = 0; tn < 8; tn++) {
                int col = n0 + tn * 8 + (lane & 3) * 2;
                float bb0 = __ldg(bp + col), bb1 = __ldg(bp + col + 1);
                if (r0g < M) {
                    float2 v = make_float2(c[i][tn][0] + bb0, c[i][tn][1] + bb1);
                    *reinterpret_cast<float2*>(op + (size_t)r0g * CH + col) = v;
                }
                if (r1g < M) {
                    float2 v = make_float2(c[i][tn][2] + bb0, c[i][tn][3] + bb1);
                    *reinterpret_cast<float2*>(op + (size_t)r1g * CH + col) = v;
                }
            }
        }
    }
}

// ---------------- edge pass 1: score + segment max --------------------------
__global__ __launch_bounds__(256) void edge_score_kernel(int E) {
    int w = (blockIdx.x * blockDim.x + threadIdx.x) >> 5;
    if (w >= E) return;
    int lane = threadIdx.x & 31;
    int s = g_src[w], d = g_dst[w];
    float4 qv = *reinterpret_cast<const float4*>(g_q + (size_t)d * CH + lane * 4);
    float4 kv = *reinterpret_cast<const float4*>(g_k + (size_t)s * CH + lane * 4);
    float p = qv.x * kv.x + qv.y * kv.y + qv.z * kv.z + qv.w * kv.w;
#pragma unroll
    for (int o = 16; o > 0; o >>= 1) p += __shfl_down_sync(0xffffffffu, p, o);
    if (lane == 0) {
        float sc = p * 0.08838834764831845f;   // 1/sqrt(128)
        g_escore[w] = sc;
        atomicMax(&g_segmax[d], enc_f(sc));
    }
}

// ---------------- edge pass 2: exp + segment sum -----------------------------
__global__ __launch_bounds__(256) void edge_exp_kernel(int E) {
    int e = blockIdx.x * blockDim.x + threadIdx.x;
    if (e >= E) return;
    int d = g_dst[e];
    float m = dec_f(g_segmax[d]);
    float ex = expf(g_escore[e] - m);
    g_eexp[e] = ex;
    atomicAdd(&g_segsum[d], ex);
}

// ---------------- edge pass 3: scatter alpha * v[src] ------------------------
__global__ __launch_bounds__(256) void edge_scatter_kernel(float* __restrict__ out, int E) {
    int w = (blockIdx.x * blockDim.x + threadIdx.x) >> 5;
    if (w >= E) return;
    int lane = threadIdx.x & 31;
    int s = g_src[w], d = g_dst[w];
    float alpha = g_eexp[w] / g_segsum[d];
    float4 vv = *reinterpret_cast<const float4*>(g_v + (size_t)s * CH + lane * 4);
    vv.x *= alpha; vv.y *= alpha; vv.z *= alpha; vv.w *= alpha;
    float* p = out + (size_t)d * CH + lane * 4;
    asm volatile("red.global.add.v4.f32 [%0], {%1, %2, %3, %4};"
                 :: "l"(p), "f"(vv.x), "f"(vv.y), "f"(vv.z), "f"(vv.w)
                 : "memory");
}

// ---------------- host ------------------------------------------------------
extern "C" void kernel_launch(void* const* d_in, const int* in_sizes, int n_in,
                              void* d_out, int out_size)
{
    const float* x    = (const float*)d_in[0];
    const void*  eidx = d_in[1];
    const float* Wq1 = (const float*)d_in[2];  const float* bq1 = (const float*)d_in[3];
    const float* Wk1 = (const float*)d_in[4];  const float* bk1 = (const float*)d_in[5];
    const float* Wv1 = (const float*)d_in[6];  const float* bv1 = (const float*)d_in[7];
    const float* Ws1 = (const float*)d_in[8];  const float* bs1 = (const float*)d_in[9];
    const float* Wq2 = (const float*)d_in[10]; const float* bq2 = (const float*)d_in[11];
    const float* Wk2 = (const float*)d_in[12]; const float* bk2 = (const float*)d_in[13];
    const float* Wv2 = (const float*)d_in[14]; const float* bv2 = (const float*)d_in[15];
    const float* Ws2 = (const float*)d_in[16]; const float* bs2 = (const float*)d_in[17];

    const int N = in_sizes[0] / CH;
    const int E = in_sizes[1] / 2;

    float *q, *k, *v, *h;
    cudaGetSymbolAddress((void**)&q, g_q);
    cudaGetSymbolAddress((void**)&k, g_k);
    cudaGetSymbolAddress((void**)&v, g_v);
    cudaGetSymbolAddress((void**)&h, g_h);
    float* out = (float*)d_out;

    cudaFuncSetAttribute(gemm4_mma_kernel<false>, cudaFuncAttributeMaxDynamicSharedMemorySize, SM_TOTAL);
    cudaFuncSetAttribute(gemm4_mma_kernel<true>,  cudaFuncAttributeMaxDynamicSharedMemorySize, SM_TOTAL);

    const int nBlocksNode = (N + 255) / 256;
    const int nBlocksEdge = (E + 255) / 256;
    const int nBlocksEdgeWarp = (int)(((long long)E * 32 + 255) / 256);
    const int nBlocksGemm = (N + 127) / 128;

    // one-time-per-call prep (cheap, deterministic)
    detect_kernel<<<1, 256>>>((const unsigned*)eidx);
    convert_edges_kernel<<<nBlocksEdge, 256>>>(eidx, E);
    prep_w_kernel<<<8, 128>>>(Wq1, Wk1, Wv1, Ws1, Wq2, Wk2, Wv2, Ws2);

    // ---------------- layer 1 ----------------
    init_seg_kernel<<<nBlocksNode, 256>>>(N);
    gemm4_mma_kernel<false><<<nBlocksGemm, 256, SM_TOTAL>>>(x, 0, bq1, bk1, bv1, bs1, q, k, v, h, N);
    edge_score_kernel<<<nBlocksEdgeWarp, 256>>>(E);
    edge_exp_kernel<<<nBlocksEdge, 256>>>(E);
    edge_scatter_kernel<<<nBlocksEdgeWarp, 256>>>(h, E);

    // ---------------- layer 2 (relu fused into A conversion) ----------------
    init_seg_kernel<<<nBlocksNode, 256>>>(N);
    gemm4_mma_kernel<true><<<nBlocksGemm, 256, SM_TOTAL>>>(h, 4, bq2, bk2, bv2, bs2, q, k, v, out, N);
    edge_score_kernel<<<nBlocksEdgeWarp, 256>>>(E);
    edge_exp_kernel<<<nBlocksEdge, 256>>>(E);
    edge_scatter_kernel<<<nBlocksEdgeWarp, 256>>>(out, E);
}

// round 6
// speedup vs baseline: 2.0693x; 1.4255x over previous
#include <cuda_runtime.h>
#include <cuda_bf16.h>
#include <math.h>
#include <stdint.h>

#define CH 128
#define N_NODES_MAX 100000
#define N_EDGES_MAX 800000
#define PITCH 136   // bf16 elems per smem row (128 + 8 pad -> conflict-free ldmatrix)

// ---------------- scratch (static device globals; no runtime allocation) ----
__device__ float g_q[(size_t)N_NODES_MAX * CH];
__device__ float g_k[(size_t)N_NODES_MAX * CH];
__device__ float g_v[(size_t)N_NODES_MAX * CH];
__device__ float g_h[(size_t)N_NODES_MAX * CH];
__device__ int g_src[N_EDGES_MAX];
__device__ int g_dst[N_EDGES_MAX];
__device__ int g_csr[N_EDGES_MAX];
__device__ int g_deg[N_NODES_MAX];
__device__ int g_off[N_NODES_MAX + 1];
__device__ int g_cursor[N_NODES_MAX];
__device__ int g_bsum[128];
__device__ int g_is64;
// pre-transposed, hi/lo-split weights: [8 matrices][n*128 + k] bf16 (B col-major)
__device__ __nv_bfloat16 g_wth[8][CH * CH];
__device__ __nv_bfloat16 g_wtl[8][CH * CH];

// ---------------- helpers ---------------------------------------------------
__device__ __forceinline__ uint32_t smem_u32(const void* p) {
    uint32_t a;
    asm("{ .reg .u64 t; cvta.to.shared.u64 t, %1; cvt.u32.u64 %0, t; }" : "=r"(a) : "l"(p));
    return a;
}
__device__ __forceinline__ void ldmatrix_x4(uint32_t* r, uint32_t addr) {
    asm volatile("ldmatrix.sync.aligned.m8n8.x4.shared.b16 {%0,%1,%2,%3}, [%4];"
                 : "=r"(r[0]), "=r"(r[1]), "=r"(r[2]), "=r"(r[3]) : "r"(addr));
}
__device__ __forceinline__ void mma_bf16(float* c, const uint32_t* a, const uint32_t* b) {
    asm volatile("mma.sync.aligned.m16n8k16.row.col.f32.bf16.bf16.f32 "
                 "{%0,%1,%2,%3}, {%4,%5,%6,%7}, {%8,%9}, {%0,%1,%2,%3};"
                 : "+f"(c[0]), "+f"(c[1]), "+f"(c[2]), "+f"(c[3])
                 : "r"(a[0]), "r"(a[1]), "r"(a[2]), "r"(a[3]), "r"(b[0]), "r"(b[1]));
}
__device__ __forceinline__ void cp_async16(uint32_t dst, const void* src) {
    asm volatile("cp.async.cg.shared.global [%0], [%1], 16;" :: "r"(dst), "l"(src));
}
#define CP_COMMIT() asm volatile("cp.async.commit_group;" ::: "memory")
#define CP_WAIT0()  asm volatile("cp.async.wait_group 0;" ::: "memory")

// ---------------- edge_index dtype detection + normalization ----------------
__global__ void detect_kernel(const unsigned* __restrict__ raw) {
    __shared__ int cnt;
    if (threadIdx.x == 0) cnt = 0;
    __syncthreads();
    int zeros = 0;
    for (int i = 1 + 2 * (int)threadIdx.x; i < 4096; i += 2 * 256)
        if (raw[i] == 0u) zeros++;
    atomicAdd(&cnt, zeros);
    __syncthreads();
    if (threadIdx.x == 0) g_is64 = (cnt > 1024) ? 1 : 0;
}

__global__ void zero_deg_kernel(int N) {
    int i = blockIdx.x * blockDim.x + threadIdx.x;
    if (i < N) g_deg[i] = 0;
}

// convert + degree count
__global__ void convert_edges_kernel(const void* __restrict__ raw, int E) {
    int i = blockIdx.x * blockDim.x + threadIdx.x;
    if (i >= E) return;
    int s, d;
    if (g_is64) {
        const long long* p = (const long long*)raw;
        s = (int)p[i]; d = (int)p[(size_t)E + i];
    } else {
        const int* p = (const int*)raw;
        s = p[i]; d = p[E + i];
    }
    g_src[i] = s; g_dst[i] = d;
    atomicAdd(&g_deg[d], 1);
}

// ---------------- CSR build: scan + scatter ---------------------------------
__global__ void scan_partial_kernel(int N) {
    __shared__ int sdata[256];
    int t = threadIdx.x;
    int base = blockIdx.x * 1024;
    int v[4], s = 0;
#pragma unroll
    for (int i = 0; i < 4; i++) {
        int idx = base + t * 4 + i;
        v[i] = (idx < N) ? g_deg[idx] : 0;
        s += v[i];
    }
    sdata[t] = s;
    __syncthreads();
    for (int off = 1; off < 256; off <<= 1) {
        int x = (t >= off) ? sdata[t - off] : 0;
        __syncthreads();
        sdata[t] += x;
        __syncthreads();
    }
    int run = sdata[t] - s;   // exclusive prefix of this thread's chunk
#pragma unroll
    for (int i = 0; i < 4; i++) {
        int idx = base + t * 4 + i;
        if (idx < N) g_off[idx] = run;
        run += v[i];
    }
    if (t == 255) g_bsum[blockIdx.x] = sdata[255];
}

__global__ void scan_bsums_kernel(int nb) {
    if (threadIdx.x == 0 && blockIdx.x == 0) {
        int run = 0;
        for (int b = 0; b < nb; b++) { int tmp = g_bsum[b]; g_bsum[b] = run; run += tmp; }
    }
}

__global__ void scan_add_kernel(int N, int E) {
    int i = blockIdx.x * blockDim.x + threadIdx.x;
    if (i < N) {
        int o = g_off[i] + g_bsum[i >> 10];
        g_off[i] = o;
        g_cursor[i] = o;
    }
    if (i == 0) g_off[N] = E;
}

__global__ void scatter_kernel(int E) {
    int i = blockIdx.x * blockDim.x + threadIdx.x;
    if (i >= E) return;
    int pos = atomicAdd(&g_cursor[g_dst[i]], 1);
    g_csr[pos] = g_src[i];
}

// ---------------- weight prep: transpose + bf16 hi/lo split -----------------
__global__ void prep_w_kernel(const float* W0, const float* W1, const float* W2, const float* W3,
                              const float* W4, const float* W5, const float* W6, const float* W7) {
    const float* Ws[8] = {W0, W1, W2, W3, W4, W5, W6, W7};
    const float* W = Ws[blockIdx.x];
    int n = threadIdx.x;   // output column -> row of transposed tile
    for (int k = 0; k < CH; k++) {
        float w = W[k * CH + n];
        __nv_bfloat16 h = __float2bfloat16(w);
        float lo = w - __bfloat162float(h);
        g_wth[blockIdx.x][n * CH + k] = h;
        g_wtl[blockIdx.x][n * CH + k] = __float2bfloat16(lo);
    }
}

// ---------------- fused 4-GEMM layer kernel (mma.sync, cp.async dbl-buf W) ---
// smem: A_hi[128][136], A_lo[128][136], Wbuf[2] each {hi[128][136], lo[128][136]}
#define TILE_B 34816                 // 128*136*2
#define SA_HI 0
#define SA_LO TILE_B
#define SW0   (2 * TILE_B)
#define WBUF_SZ (2 * TILE_B)         // hi + lo
#define SM_TOTAL (2 * TILE_B + 2 * WBUF_SZ)   // 208896

template<bool RELU>
__global__ __launch_bounds__(256, 1) void gemm4_mma_kernel(
    const float* __restrict__ A, int wbase,
    const float* __restrict__ b0, const float* __restrict__ b1,
    const float* __restrict__ b2, const float* __restrict__ b3,
    float* __restrict__ o0, float* __restrict__ o1,
    float* __restrict__ o2, float* __restrict__ o3, int M)
{
    extern __shared__ char smem[];
    const uint32_t sb = smem_u32(smem);
    const int tid = threadIdx.x;
    const int lane = tid & 31;
    const int warp = tid >> 5;
    const int m0 = (warp >> 1) * 32;
    const int n0 = (warp & 1) * 64;
    const int row0 = blockIdx.x * 128;

    // ---- A tile: fp32 load -> hi/lo bf16 split into padded smem -------------
#pragma unroll
    for (int i = 0; i < 16; i++) {
        int idx = i * 256 + tid;
        int row = idx >> 5, c4 = idx & 31;
        int gr = row0 + row;
        float4 xv = make_float4(0.f, 0.f, 0.f, 0.f);
        if (gr < M) xv = *reinterpret_cast<const float4*>(A + (size_t)gr * CH + c4 * 4);
        if (RELU) {
            xv.x = fmaxf(xv.x, 0.f); xv.y = fmaxf(xv.y, 0.f);
            xv.z = fmaxf(xv.z, 0.f); xv.w = fmaxf(xv.w, 0.f);
        }
        __nv_bfloat16 h0 = __float2bfloat16(xv.x), h1 = __float2bfloat16(xv.y);
        __nv_bfloat16 h2 = __float2bfloat16(xv.z), h3 = __float2bfloat16(xv.w);
        float l0 = xv.x - __bfloat162float(h0), l1 = xv.y - __bfloat162float(h1);
        float l2 = xv.z - __bfloat162float(h2), l3 = xv.w - __bfloat162float(h3);
        __nv_bfloat16 hs[4] = {h0, h1, h2, h3};
        __nv_bfloat16 ls[4] = {__float2bfloat16(l0), __float2bfloat16(l1),
                               __float2bfloat16(l2), __float2bfloat16(l3)};
        uint32_t off = (uint32_t)(row * PITCH + c4 * 4) * 2;
        *reinterpret_cast<uint2*>(smem + SA_HI + off) = *reinterpret_cast<uint2*>(hs);
        *reinterpret_cast<uint2*>(smem + SA_LO + off) = *reinterpret_cast<uint2*>(ls);
    }

    // issue W for j=0 into buffer 0 (cp.async, one group)
    {
        const __nv_bfloat16* wh = g_wth[wbase];
        const __nv_bfloat16* wl = g_wtl[wbase];
#pragma unroll
        for (int i = 0; i < 8; i++) {
            int idx = i * 256 + tid;
            int n = idx >> 4, k0 = (idx & 15) * 8;
            uint32_t doff = sb + SW0 + (uint32_t)(n * PITCH + k0) * 2;
            cp_async16(doff, wh + n * CH + k0);
            cp_async16(doff + TILE_B, wl + n * CH + k0);
        }
        CP_COMMIT();
    }

    const int a_row = (lane & 15);
    const int a_col = (lane >> 4) << 3;
    const int b_nrow = (lane & 7) + ((lane & 16) ? 8 : 0);
    const int b_kcol = (lane & 8) ? 8 : 0;

    const float* biases[4] = {b0, b1, b2, b3};
    float* outs[4] = {o0, o1, o2, o3};

#pragma unroll
    for (int j = 0; j < 4; j++) {
        CP_WAIT0();          // this thread's group for j complete
        __syncthreads();     // all threads' groups complete; also A visible (j=0),
                             // and prior readers of the other buffer are done
        // prefetch j+1 into the alternate buffer; overlaps with MMA below
        if (j < 3) {
            const __nv_bfloat16* wh = g_wth[wbase + j + 1];
            const __nv_bfloat16* wl = g_wtl[wbase + j + 1];
            uint32_t wb = sb + SW0 + (uint32_t)(((j + 1) & 1) * WBUF_SZ);
#pragma unroll
            for (int i = 0; i < 8; i++) {
                int idx = i * 256 + tid;
                int n = idx >> 4, k0 = (idx & 15) * 8;
                uint32_t doff = wb + (uint32_t)(n * PITCH + k0) * 2;
                cp_async16(doff, wh + n * CH + k0);
                cp_async16(doff + TILE_B, wl + n * CH + k0);
            }
            CP_COMMIT();
        }

        const uint32_t wbase_hi = sb + SW0 + (uint32_t)((j & 1) * WBUF_SZ);
        const uint32_t wbase_lo = wbase_hi + TILE_B;

        float c[2][8][4];
#pragma unroll
        for (int i = 0; i < 2; i++)
#pragma unroll
            for (int tn = 0; tn < 8; tn++)
#pragma unroll
                for (int e = 0; e < 4; e++) c[i][tn][e] = 0.0f;

#pragma unroll
        for (int ks = 0; ks < 8; ks++) {
            const int k = ks * 16;
            // A frags (hi & lo)
            uint32_t ah[2][4], al[2][4];
#pragma unroll
            for (int i = 0; i < 2; i++) {
                uint32_t ao = (uint32_t)((m0 + i * 16 + a_row) * PITCH + k + a_col) * 2;
                ldmatrix_x4(ah[i], sb + SA_HI + ao);
                ldmatrix_x4(al[i], sb + SA_LO + ao);
            }
            uint32_t bfr[8][2];
            // --- Whi: terms Ahi*Whi + Alo*Whi
#pragma unroll
            for (int q = 0; q < 4; q++) {
                uint32_t r[4];
                ldmatrix_x4(r, wbase_hi +
                    (uint32_t)((n0 + q * 16 + b_nrow) * PITCH + k + b_kcol) * 2);
                bfr[q * 2][0] = r[0]; bfr[q * 2][1] = r[1];
                bfr[q * 2 + 1][0] = r[2]; bfr[q * 2 + 1][1] = r[3];
            }
#pragma unroll
            for (int i = 0; i < 2; i++)
#pragma unroll
                for (int tn = 0; tn < 8; tn++) {
                    mma_bf16(c[i][tn], ah[i], bfr[tn]);
                    mma_bf16(c[i][tn], al[i], bfr[tn]);
                }
            // --- Wlo: term Ahi*Wlo
#pragma unroll
            for (int q = 0; q < 4; q++) {
                uint32_t r[4];
                ldmatrix_x4(r, wbase_lo +
                    (uint32_t)((n0 + q * 16 + b_nrow) * PITCH + k + b_kcol) * 2);
                bfr[q * 2][0] = r[0]; bfr[q * 2][1] = r[1];
                bfr[q * 2 + 1][0] = r[2]; bfr[q * 2 + 1][1] = r[3];
            }
#pragma unroll
            for (int i = 0; i < 2; i++)
#pragma unroll
                for (int tn = 0; tn < 8; tn++)
                    mma_bf16(c[i][tn], ah[i], bfr[tn]);
        }

        // ---- epilogue j (registers only; overlaps next j's cp.async) --------
        const float* bp = biases[j];
        float* op = outs[j];
#pragma unroll
        for (int i = 0; i < 2; i++) {
            int r0g = row0 + m0 + i * 16 + (lane >> 2);
            int r1g = r0g + 8;
#pragma unroll
            for (int tn = 0; tn < 8; tn++) {
                int col = n0 + tn * 8 + (lane & 3) * 2;
                float bb0 = __ldg(bp + col), bb1 = __ldg(bp + col + 1);
                if (r0g < M) {
                    float2 vo = make_float2(c[i][tn][0] + bb0, c[i][tn][1] + bb1);
                    *reinterpret_cast<float2*>(op + (size_t)r0g * CH + col) = vo;
                }
                if (r1g < M) {
                    float2 vo = make_float2(c[i][tn][2] + bb0, c[i][tn][3] + bb1);
                    *reinterpret_cast<float2*>(op + (size_t)r1g * CH + col) = vo;
                }
            }
        }
    }
}

// ---------------- fused CSR attention: warp per destination node -------------
// online softmax over the node's edge list; no atomics; out += sum(alpha*v[src])
__global__ __launch_bounds__(256) void attn_kernel(float* __restrict__ out, int N) {
    int node = (blockIdx.x * blockDim.x + threadIdx.x) >> 5;
    if (node >= N) return;
    int lane = threadIdx.x & 31;
    int beg = g_off[node], end = g_off[node + 1];
    if (beg == end) return;

    float4 qv = *reinterpret_cast<const float4*>(g_q + (size_t)node * CH + lane * 4);
    float m = -1e30f, l = 0.0f;
    float4 acc = make_float4(0.f, 0.f, 0.f, 0.f);

    int s = g_csr[beg];
    float4 kv = *reinterpret_cast<const float4*>(g_k + (size_t)s * CH + lane * 4);
    float4 vv = *reinterpret_cast<const float4*>(g_v + (size_t)s * CH + lane * 4);

    for (int e = beg; e < end; e++) {
        float4 kn, vn;
        if (e + 1 < end) {                      // prefetch next row pair
            int sn = g_csr[e + 1];
            kn = *reinterpret_cast<const float4*>(g_k + (size_t)sn * CH + lane * 4);
            vn = *reinterpret_cast<const float4*>(g_v + (size_t)sn * CH + lane * 4);
        }
        float dot = qv.x * kv.x + qv.y * kv.y + qv.z * kv.z + qv.w * kv.w;
#pragma unroll
        for (int o = 16; o > 0; o >>= 1) dot += __shfl_xor_sync(0xffffffffu, dot, o);
        float sc = dot * 0.08838834764831845f;  // 1/sqrt(128)
        float nm = fmaxf(m, sc);
        float scale = expf(m - nm);
        float p = expf(sc - nm);
        l = l * scale + p;
        acc.x = acc.x * scale + p * vv.x;
        acc.y = acc.y * scale + p * vv.y;
        acc.z = acc.z * scale + p * vv.z;
        acc.w = acc.w * scale + p * vv.w;
        m = nm;
        kv = kn; vv = vn;
    }
    float inv = 1.0f / l;
    float* op = out + (size_t)node * CH + lane * 4;
    float4 o = *reinterpret_cast<float4*>(op);
    o.x += acc.x * inv; o.y += acc.y * inv;
    o.z += acc.z * inv; o.w += acc.w * inv;
    *reinterpret_cast<float4*>(op) = o;
}

// ---------------- host ------------------------------------------------------
extern "C" void kernel_launch(void* const* d_in, const int* in_sizes, int n_in,
                              void* d_out, int out_size)
{
    const float* x    = (const float*)d_in[0];
    const void*  eidx = d_in[1];
    const float* Wq1 = (const float*)d_in[2];  const float* bq1 = (const float*)d_in[3];
    const float* Wk1 = (const float*)d_in[4];  const float* bk1 = (const float*)d_in[5];
    const float* Wv1 = (const float*)d_in[6];  const float* bv1 = (const float*)d_in[7];
    const float* Ws1 = (const float*)d_in[8];  const float* bs1 = (const float*)d_in[9];
    const float* Wq2 = (const float*)d_in[10]; const float* bq2 = (const float*)d_in[11];
    const float* Wk2 = (const float*)d_in[12]; const float* bk2 = (const float*)d_in[13];
    const float* Wv2 = (const float*)d_in[14]; const float* bv2 = (const float*)d_in[15];
    const float* Ws2 = (const float*)d_in[16]; const float* bs2 = (const float*)d_in[17];

    const int N = in_sizes[0] / CH;
    const int E = in_sizes[1] / 2;

    float *q, *k, *v, *h;
    cudaGetSymbolAddress((void**)&q, g_q);
    cudaGetSymbolAddress((void**)&k, g_k);
    cudaGetSymbolAddress((void**)&v, g_v);
    cudaGetSymbolAddress((void**)&h, g_h);
    float* out = (float*)d_out;

    cudaFuncSetAttribute(gemm4_mma_kernel<false>, cudaFuncAttributeMaxDynamicSharedMemorySize, SM_TOTAL);
    cudaFuncSetAttribute(gemm4_mma_kernel<true>,  cudaFuncAttributeMaxDynamicSharedMemorySize, SM_TOTAL);

    const int nBlocksNode = (N + 255) / 256;
    const int nBlocksEdge = (E + 255) / 256;
    const int nBlocksGemm = (N + 127) / 128;
    const int nBlocksAttn = (N * 32 + 255) / 256;
    const int nbScan = (N + 1023) / 1024;

    // ---- prep: edges -> int32, CSR by dst, weight split ----
    detect_kernel<<<1, 256>>>((const unsigned*)eidx);
    zero_deg_kernel<<<nBlocksNode, 256>>>(N);
    convert_edges_kernel<<<nBlocksEdge, 256>>>(eidx, E);
    scan_partial_kernel<<<nbScan, 256>>>(N);
    scan_bsums_kernel<<<1, 32>>>(nbScan);
    scan_add_kernel<<<nBlocksNode, 256>>>(N, E);
    scatter_kernel<<<nBlocksEdge, 256>>>(E);
    prep_w_kernel<<<8, 128>>>(Wq1, Wk1, Wv1, Ws1, Wq2, Wk2, Wv2, Ws2);

    // ---- layer 1 ----
    gemm4_mma_kernel<false><<<nBlocksGemm, 256, SM_TOTAL>>>(x, 0, bq1, bk1, bv1, bs1, q, k, v, h, N);
    attn_kernel<<<nBlocksAttn, 256>>>(h, N);

    // ---- layer 2 (relu fused into A conversion) ----
    gemm4_mma_kernel<true><<<nBlocksGemm, 256, SM_TOTAL>>>(h, 4, bq2, bk2, bv2, bs2, q, k, v, out, N);
    attn_kernel<<<nBlocksAttn, 256>>>(out, N);
}

// round 7
// speedup vs baseline: 2.4656x; 1.1915x over previous
#include <cuda_runtime.h>
#include <cuda_fp16.h>
#include <math.h>
#include <stdint.h>

#define CH 128
#define N_NODES_MAX 100000
#define N_EDGES_MAX 800000
#define PITCH 136   // fp16 elems per smem row (128 + 8 pad -> conflict-free ldmatrix)

// ---------------- scratch (static device globals; no runtime allocation) ----
__device__ float g_q[(size_t)N_NODES_MAX * CH];
__device__ float g_k[(size_t)N_NODES_MAX * CH];
__device__ float g_v[(size_t)N_NODES_MAX * CH];
__device__ float g_h[(size_t)N_NODES_MAX * CH];
__device__ int g_src[N_EDGES_MAX];
__device__ int g_dst[N_EDGES_MAX];
__device__ int g_csr[N_EDGES_MAX];
__device__ int g_deg[N_NODES_MAX];
__device__ int g_off[N_NODES_MAX + 1];
__device__ int g_cursor[N_NODES_MAX];
__device__ int g_bsum[128];
__device__ int g_is64;
// pre-transposed fp16 weights: [8 matrices][n*128 + k]  (B col-major for mma)
__device__ __half g_wt[8][CH * CH];

// ---------------- helpers ---------------------------------------------------
__device__ __forceinline__ uint32_t smem_u32(const void* p) {
    uint32_t a;
    asm("{ .reg .u64 t; cvta.to.shared.u64 t, %1; cvt.u32.u64 %0, t; }" : "=r"(a) : "l"(p));
    return a;
}
__device__ __forceinline__ void ldmatrix_x4(uint32_t* r, uint32_t addr) {
    asm volatile("ldmatrix.sync.aligned.m8n8.x4.shared.b16 {%0,%1,%2,%3}, [%4];"
                 : "=r"(r[0]), "=r"(r[1]), "=r"(r[2]), "=r"(r[3]) : "r"(addr));
}
__device__ __forceinline__ void mma_f16(float* c, const uint32_t* a, const uint32_t* b) {
    asm volatile("mma.sync.aligned.m16n8k16.row.col.f32.f16.f16.f32 "
                 "{%0,%1,%2,%3}, {%4,%5,%6,%7}, {%8,%9}, {%0,%1,%2,%3};"
                 : "+f"(c[0]), "+f"(c[1]), "+f"(c[2]), "+f"(c[3])
                 : "r"(a[0]), "r"(a[1]), "r"(a[2]), "r"(a[3]), "r"(b[0]), "r"(b[1]));
}
__device__ __forceinline__ void cp_async16(uint32_t dst, const void* src) {
    asm volatile("cp.async.cg.shared.global [%0], [%1], 16;" :: "r"(dst), "l"(src));
}
#define CP_COMMIT() asm volatile("cp.async.commit_group;" ::: "memory")
#define CP_WAIT0()  asm volatile("cp.async.wait_group 0;" ::: "memory")

// ---------------- edge_index dtype detection + normalization ----------------
__global__ void detect_kernel(const unsigned* __restrict__ raw) {
    __shared__ int cnt;
    if (threadIdx.x == 0) cnt = 0;
    __syncthreads();
    int zeros = 0;
    for (int i = 1 + 2 * (int)threadIdx.x; i < 4096; i += 2 * 256)
        if (raw[i] == 0u) zeros++;
    atomicAdd(&cnt, zeros);
    __syncthreads();
    if (threadIdx.x == 0) g_is64 = (cnt > 1024) ? 1 : 0;
}

__global__ void zero_deg_kernel(int N) {
    int i = blockIdx.x * blockDim.x + threadIdx.x;
    if (i < N) g_deg[i] = 0;
}

__global__ void convert_edges_kernel(const void* __restrict__ raw, int E) {
    int i = blockIdx.x * blockDim.x + threadIdx.x;
    if (i >= E) return;
    int s, d;
    if (g_is64) {
        const long long* p = (const long long*)raw;
        s = (int)p[i]; d = (int)p[(size_t)E + i];
    } else {
        const int* p = (const int*)raw;
        s = p[i]; d = p[E + i];
    }
    g_src[i] = s; g_dst[i] = d;
    atomicAdd(&g_deg[d], 1);
}

// ---------------- CSR build: scan + scatter ---------------------------------
__global__ void scan_partial_kernel(int N) {
    __shared__ int sdata[256];
    int t = threadIdx.x;
    int base = blockIdx.x * 1024;
    int v[4], s = 0;
#pragma unroll
    for (int i = 0; i < 4; i++) {
        int idx = base + t * 4 + i;
        v[i] = (idx < N) ? g_deg[idx] : 0;
        s += v[i];
    }
    sdata[t] = s;
    __syncthreads();
    for (int off = 1; off < 256; off <<= 1) {
        int x = (t >= off) ? sdata[t - off] : 0;
        __syncthreads();
        sdata[t] += x;
        __syncthreads();
    }
    int run = sdata[t] - s;
#pragma unroll
    for (int i = 0; i < 4; i++) {
        int idx = base + t * 4 + i;
        if (idx < N) g_off[idx] = run;
        run += v[i];
    }
    if (t == 255) g_bsum[blockIdx.x] = sdata[255];
}

__global__ void scan_bsums_kernel(int nb) {
    if (threadIdx.x == 0 && blockIdx.x == 0) {
        int run = 0;
        for (int b = 0; b < nb; b++) { int tmp = g_bsum[b]; g_bsum[b] = run; run += tmp; }
    }
}

__global__ void scan_add_kernel(int N, int E) {
    int i = blockIdx.x * blockDim.x + threadIdx.x;
    if (i < N) {
        int o = g_off[i] + g_bsum[i >> 10];
        g_off[i] = o;
        g_cursor[i] = o;
    }
    if (i == 0) g_off[N] = E;
}

__global__ void scatter_kernel(int E) {
    int i = blockIdx.x * blockDim.x + threadIdx.x;
    if (i >= E) return;
    int pos = atomicAdd(&g_cursor[g_dst[i]], 1);
    g_csr[pos] = g_src[i];
}

// ---------------- weight prep: transpose + fp16 round -----------------------
__global__ void prep_w_kernel(const float* W0, const float* W1, const float* W2, const float* W3,
                              const float* W4, const float* W5, const float* W6, const float* W7) {
    const float* Ws[8] = {W0, W1, W2, W3, W4, W5, W6, W7};
    const float* W = Ws[blockIdx.x];
    int n = threadIdx.x;   // output column -> row of transposed tile
    for (int k = 0; k < CH; k++)
        g_wt[blockIdx.x][n * CH + k] = __float2half_rn(W[k * CH + n]);
}

// ---------------- fused 4-GEMM layer kernel (mma.sync fp16, 2-term split) ----
// smem: A_hi[128][136], A_lo[128][136], W[128][136] (fp16). 102 KB -> 2 CTA/SM.
#define TILE_B 34816                 // 128*136*2
#define SA_HI 0
#define SA_LO TILE_B
#define SW    (2 * TILE_B)
#define SM_TOTAL (3 * TILE_B)        // 104448

template<bool RELU>
__global__ __launch_bounds__(256, 2) void gemm4_mma_kernel(
    const float* __restrict__ A, int wbase,
    const float* __restrict__ b0, const float* __restrict__ b1,
    const float* __restrict__ b2, const float* __restrict__ b3,
    float* __restrict__ o0, float* __restrict__ o1,
    float* __restrict__ o2, float* __restrict__ o3, int M)
{
    extern __shared__ char smem[];
    const uint32_t sb = smem_u32(smem);
    const int tid = threadIdx.x;
    const int lane = tid & 31;
    const int warp = tid >> 5;
    const int m0 = (warp >> 1) * 32;
    const int n0 = (warp & 1) * 64;
    const int row0 = blockIdx.x * 128;

    // prefetch W for j=0 (overlaps with A conversion below)
    {
        const __half* w = g_wt[wbase];
#pragma unroll
        for (int i = 0; i < 8; i++) {
            int idx = i * 256 + tid;              // 2048 uint4
            int n = idx >> 4, k0 = (idx & 15) * 8;
            cp_async16(sb + SW + (uint32_t)(n * PITCH + k0) * 2, w + n * CH + k0);
        }
        CP_COMMIT();
    }

    // ---- A tile: fp32 load -> hi/lo fp16 split into padded smem -------------
#pragma unroll
    for (int i = 0; i < 16; i++) {
        int idx = i * 256 + tid;
        int row = idx >> 5, c4 = idx & 31;
        int gr = row0 + row;
        float4 xv = make_float4(0.f, 0.f, 0.f, 0.f);
        if (gr < M) xv = *reinterpret_cast<const float4*>(A + (size_t)gr * CH + c4 * 4);
        if (RELU) {
            xv.x = fmaxf(xv.x, 0.f); xv.y = fmaxf(xv.y, 0.f);
            xv.z = fmaxf(xv.z, 0.f); xv.w = fmaxf(xv.w, 0.f);
        }
        __half h0 = __float2half_rn(xv.x), h1 = __float2half_rn(xv.y);
        __half h2 = __float2half_rn(xv.z), h3 = __float2half_rn(xv.w);
        float l0 = xv.x - __half2float(h0), l1 = xv.y - __half2float(h1);
        float l2 = xv.z - __half2float(h2), l3 = xv.w - __half2float(h3);
        __half hs[4] = {h0, h1, h2, h3};
        __half ls[4] = {__float2half_rn(l0), __float2half_rn(l1),
                        __float2half_rn(l2), __float2half_rn(l3)};
        uint32_t off = (uint32_t)(row * PITCH + c4 * 4) * 2;
        *reinterpret_cast<uint2*>(smem + SA_HI + off) = *reinterpret_cast<uint2*>(hs);
        *reinterpret_cast<uint2*>(smem + SA_LO + off) = *reinterpret_cast<uint2*>(ls);
    }
    CP_WAIT0();
    __syncthreads();

    const int a_row = (lane & 15);
    const int a_col = (lane >> 4) << 3;
    const int b_nrow = (lane & 7) + ((lane & 16) ? 8 : 0);
    const int b_kcol = (lane & 8) ? 8 : 0;

    const float* biases[4] = {b0, b1, b2, b3};
    float* outs[4] = {o0, o1, o2, o3};

#pragma unroll
    for (int j = 0; j < 4; j++) {
        float c[2][8][4];
#pragma unroll
        for (int i = 0; i < 2; i++)
#pragma unroll
            for (int tn = 0; tn < 8; tn++)
#pragma unroll
                for (int e = 0; e < 4; e++) c[i][tn][e] = 0.0f;

#pragma unroll
        for (int ks = 0; ks < 8; ks++) {
            const int k = ks * 16;
            uint32_t ah[2][4], al[2][4];
#pragma unroll
            for (int i = 0; i < 2; i++) {
                uint32_t ao = (uint32_t)((m0 + i * 16 + a_row) * PITCH + k + a_col) * 2;
                ldmatrix_x4(ah[i], sb + SA_HI + ao);
                ldmatrix_x4(al[i], sb + SA_LO + ao);
            }
            uint32_t bfr[8][2];
#pragma unroll
            for (int q = 0; q < 4; q++) {
                uint32_t r[4];
                ldmatrix_x4(r, sb + SW +
                    (uint32_t)((n0 + q * 16 + b_nrow) * PITCH + k + b_kcol) * 2);
                bfr[q * 2][0] = r[0]; bfr[q * 2][1] = r[1];
                bfr[q * 2 + 1][0] = r[2]; bfr[q * 2 + 1][1] = r[3];
            }
#pragma unroll
            for (int i = 0; i < 2; i++)
#pragma unroll
                for (int tn = 0; tn < 8; tn++) {
                    mma_f16(c[i][tn], ah[i], bfr[tn]);
                    mma_f16(c[i][tn], al[i], bfr[tn]);
                }
        }

        // ---- epilogue j: bias + store (registers/global only) ---------------
        const float* bp = biases[j];
        float* op = outs[j];
#pragma unroll
        for (int i = 0; i < 2; i++) {
            int r0g = row0 + m0 + i * 16 + (lane >> 2);
            int r1g = r0g + 8;
#pragma unroll
            for (int tn = 0; tn < 8; tn++) {
                int col = n0 + tn * 8 + (lane & 3) * 2;
                float bb0 = __ldg(bp + col), bb1 = __ldg(bp + col + 1);
                if (r0g < M) {
                    float2 vo = make_float2(c[i][tn][0] + bb0, c[i][tn][1] + bb1);
                    *reinterpret_cast<float2*>(op + (size_t)r0g * CH + col) = vo;
                }
                if (r1g < M) {
                    float2 vo = make_float2(c[i][tn][2] + bb0, c[i][tn][3] + bb1);
                    *reinterpret_cast<float2*>(op + (size_t)r1g * CH + col) = vo;
                }
            }
        }

        // ---- load W for j+1 into the (single) W buffer ----------------------
        if (j < 3) {
            __syncthreads();      // all warps done reading SW for j
            const __half* w = g_wt[wbase + j + 1];
#pragma unroll
            for (int i = 0; i < 8; i++) {
                int idx = i * 256 + tid;
                int n = idx >> 4, k0 = (idx & 15) * 8;
                cp_async16(sb + SW + (uint32_t)(n * PITCH + k0) * 2, w + n * CH + k0);
            }
            CP_COMMIT();
            CP_WAIT0();
            __syncthreads();
        }
    }
}

// ---------------- fused CSR attention: warp per destination node -------------
__global__ __launch_bounds__(256) void attn_kernel(float* __restrict__ out, int N) {
    int node = (blockIdx.x * blockDim.x + threadIdx.x) >> 5;
    if (node >= N) return;
    int lane = threadIdx.x & 31;
    int beg = g_off[node], end = g_off[node + 1];
    if (beg == end) return;

    float4 qv = *reinterpret_cast<const float4*>(g_q + (size_t)node * CH + lane * 4);
    float m = -1e30f, l = 0.0f;
    float4 acc = make_float4(0.f, 0.f, 0.f, 0.f);

    int s = g_csr[beg];
    float4 kv = *reinterpret_cast<const float4*>(g_k + (size_t)s * CH + lane * 4);
    float4 vv = *reinterpret_cast<const float4*>(g_v + (size_t)s * CH + lane * 4);

    for (int e = beg; e < end; e++) {
        float4 kn, vn;
        if (e + 1 < end) {
            int sn = g_csr[e + 1];
            kn = *reinterpret_cast<const float4*>(g_k + (size_t)sn * CH + lane * 4);
            vn = *reinterpret_cast<const float4*>(g_v + (size_t)sn * CH + lane * 4);
        }
        float dot = qv.x * kv.x + qv.y * kv.y + qv.z * kv.z + qv.w * kv.w;
#pragma unroll
        for (int o = 16; o > 0; o >>= 1) dot += __shfl_xor_sync(0xffffffffu, dot, o);
        float sc = dot * 0.08838834764831845f;  // 1/sqrt(128)
        float nm = fmaxf(m, sc);
        float scale = expf(m - nm);
        float p = expf(sc - nm);
        l = l * scale + p;
        acc.x = acc.x * scale + p * vv.x;
        acc.y = acc.y * scale + p * vv.y;
        acc.z = acc.z * scale + p * vv.z;
        acc.w = acc.w * scale + p * vv.w;
        m = nm;
        kv = kn; vv = vn;
    }
    float inv = 1.0f / l;
    float* op = out + (size_t)node * CH + lane * 4;
    float4 o = *reinterpret_cast<float4*>(op);
    o.x += acc.x * inv; o.y += acc.y * inv;
    o.z += acc.z * inv; o.w += acc.w * inv;
    *reinterpret_cast<float4*>(op) = o;
}

// ---------------- host ------------------------------------------------------
extern "C" void kernel_launch(void* const* d_in, const int* in_sizes, int n_in,
                              void* d_out, int out_size)
{
    const float* x    = (const float*)d_in[0];
    const void*  eidx = d_in[1];
    const float* Wq1 = (const float*)d_in[2];  const float* bq1 = (const float*)d_in[3];
    const float* Wk1 = (const float*)d_in[4];  const float* bk1 = (const float*)d_in[5];
    const float* Wv1 = (const float*)d_in[6];  const float* bv1 = (const float*)d_in[7];
    const float* Ws1 = (const float*)d_in[8];  const float* bs1 = (const float*)d_in[9];
    const float* Wq2 = (const float*)d_in[10]; const float* bq2 = (const float*)d_in[11];
    const float* Wk2 = (const float*)d_in[12]; const float* bk2 = (const float*)d_in[13];
    const float* Wv2 = (const float*)d_in[14]; const float* bv2 = (const float*)d_in[15];
    const float* Ws2 = (const float*)d_in[16]; const float* bs2 = (const float*)d_in[17];

    const int N = in_sizes[0] / CH;
    const int E = in_sizes[1] / 2;

    float *q, *k, *v, *h;
    cudaGetSymbolAddress((void**)&q, g_q);
    cudaGetSymbolAddress((void**)&k, g_k);
    cudaGetSymbolAddress((void**)&v, g_v);
    cudaGetSymbolAddress((void**)&h, g_h);
    float* out = (float*)d_out;

    cudaFuncSetAttribute(gemm4_mma_kernel<false>, cudaFuncAttributeMaxDynamicSharedMemorySize, SM_TOTAL);
    cudaFuncSetAttribute(gemm4_mma_kernel<true>,  cudaFuncAttributeMaxDynamicSharedMemorySize, SM_TOTAL);

    const int nBlocksNode = (N + 255) / 256;
    const int nBlocksEdge = (E + 255) / 256;
    const int nBlocksGemm = (N + 127) / 128;
    const int nBlocksAttn = (N * 32 + 255) / 256;
    const int nbScan = (N + 1023) / 1024;

    // ---- prep: edges -> int32, CSR by dst, weight transpose/round ----
    detect_kernel<<<1, 256>>>((const unsigned*)eidx);
    zero_deg_kernel<<<nBlocksNode, 256>>>(N);
    convert_edges_kernel<<<nBlocksEdge, 256>>>(eidx, E);
    scan_partial_kernel<<<nbScan, 256>>>(N);
    scan_bsums_kernel<<<1, 32>>>(nbScan);
    scan_add_kernel<<<nBlocksNode, 256>>>(N, E);
    scatter_kernel<<<nBlocksEdge, 256>>>(E);
    prep_w_kernel<<<8, 128>>>(Wq1, Wk1, Wv1, Ws1, Wq2, Wk2, Wv2, Ws2);

    // ---- layer 1 ----
    gemm4_mma_kernel<false><<<nBlocksGemm, 256, SM_TOTAL>>>(x, 0, bq1, bk1, bv1, bs1, q, k, v, h, N);
    attn_kernel<<<nBlocksAttn, 256>>>(h, N);

    // ---- layer 2 (relu fused into A conversion) ----
    gemm4_mma_kernel<true><<<nBlocksGemm, 256, SM_TOTAL>>>(h, 4, bq2, bk2, bv2, bs2, q, k, v, out, N);
    attn_kernel<<<nBlocksAttn, 256>>>(out, N);
}

// round 9
// speedup vs baseline: 2.6367x; 1.0694x over previous
#include <cuda_runtime.h>
#include <cuda_fp16.h>
#include <math.h>
#include <stdint.h>

#define CH 128
#define N_NODES_MAX 100000
#define N_EDGES_MAX 800000
#define PITCH 136   // fp16 elems per smem row (128 + 8 pad -> conflict-free ldmatrix)

// ---------------- scratch (static device globals; no runtime allocation) ----
__device__ float g_q[(size_t)N_NODES_MAX * CH];
__device__ __half g_kh[(size_t)N_NODES_MAX * CH];
__device__ __half g_vh[(size_t)N_NODES_MAX * CH];
__device__ float g_h[(size_t)N_NODES_MAX * CH];
__device__ int g_src[N_EDGES_MAX];
__device__ int g_dst[N_EDGES_MAX];
__device__ int g_csr[N_EDGES_MAX];
__device__ int g_deg[N_NODES_MAX];
__device__ int g_off[N_NODES_MAX + 1];
__device__ int g_cursor[N_NODES_MAX];
__device__ int g_bsum[128];
__device__ int g_is64;
// pre-transposed fp16 weights: [8 matrices][n*128 + k]  (B col-major for mma)
__device__ __half g_wt[8][CH * CH];

// ---------------- helpers ---------------------------------------------------
__device__ __forceinline__ uint32_t smem_u32(const void* p) {
    uint32_t a;
    asm("{ .reg .u64 t; cvta.to.shared.u64 t, %1; cvt.u32.u64 %0, t; }" : "=r"(a) : "l"(p));
    return a;
}
__device__ __forceinline__ void ldmatrix_x4(uint32_t* r, uint32_t addr) {
    asm volatile("ldmatrix.sync.aligned.m8n8.x4.shared.b16 {%0,%1,%2,%3}, [%4];"
                 : "=r"(r[0]), "=r"(r[1]), "=r"(r[2]), "=r"(r[3]) : "r"(addr));
}
__device__ __forceinline__ void mma_f16(float* c, const uint32_t* a, const uint32_t* b) {
    asm volatile("mma.sync.aligned.m16n8k16.row.col.f32.f16.f16.f32 "
                 "{%0,%1,%2,%3}, {%4,%5,%6,%7}, {%8,%9}, {%0,%1,%2,%3};"
                 : "+f"(c[0]), "+f"(c[1]), "+f"(c[2]), "+f"(c[3])
                 : "r"(a[0]), "r"(a[1]), "r"(a[2]), "r"(a[3]), "r"(b[0]), "r"(b[1]));
}
__device__ __forceinline__ void cp_async16(uint32_t dst, const void* src) {
    asm volatile("cp.async.cg.shared.global [%0], [%1], 16;" :: "r"(dst), "l"(src));
}
#define CP_COMMIT() asm volatile("cp.async.commit_group;" ::: "memory")
#define CP_WAIT0()  asm volatile("cp.async.wait_group 0;" ::: "memory")

// ---------------- edge_index dtype detection + normalization ----------------
__global__ void detect_kernel(const unsigned* __restrict__ raw) {
    __shared__ int cnt;
    if (threadIdx.x == 0) cnt = 0;
    __syncthreads();
    int zeros = 0;
    for (int i = 1 + 2 * (int)threadIdx.x; i < 4096; i += 2 * 256)
        if (raw[i] == 0u) zeros++;
    atomicAdd(&cnt, zeros);
    __syncthreads();
    if (threadIdx.x == 0) g_is64 = (cnt > 1024) ? 1 : 0;
}

__global__ void zero_deg_kernel(int N) {
    int i = blockIdx.x * blockDim.x + threadIdx.x;
    if (i < N) g_deg[i] = 0;
}

__global__ void convert_edges_kernel(const void* __restrict__ raw, int E) {
    int i = blockIdx.x * blockDim.x + threadIdx.x;
    if (i >= E) return;
    int s, d;
    if (g_is64) {
        const long long* p = (const long long*)raw;
        s = (int)p[i]; d = (int)p[(size_t)E + i];
    } else {
        const int* p = (const int*)raw;
        s = p[i]; d = p[E + i];
    }
    g_src[i] = s; g_dst[i] = d;
    atomicAdd(&g_deg[d], 1);
}

// ---------------- CSR build: scan + scatter ---------------------------------
__global__ void scan_partial_kernel(int N) {
    __shared__ int sdata[256];
    int t = threadIdx.x;
    int base = blockIdx.x * 1024;
    int v[4], s = 0;
#pragma unroll
    for (int i = 0; i < 4; i++) {
        int idx = base + t * 4 + i;
        v[i] = (idx < N) ? g_deg[idx] : 0;
        s += v[i];
    }
    sdata[t] = s;
    __syncthreads();
    for (int off = 1; off < 256; off <<= 1) {
        int x = (t >= off) ? sdata[t - off] : 0;
        __syncthreads();
        sdata[t] += x;
        __syncthreads();
    }
    int run = sdata[t] - s;
#pragma unroll
    for (int i = 0; i < 4; i++) {
        int idx = base + t * 4 + i;
        if (idx < N) g_off[idx] = run;
        run += v[i];
    }
    if (t == 255) g_bsum[blockIdx.x] = sdata[255];
}

__global__ void scan_bsums_kernel(int nb) {
    if (threadIdx.x == 0 && blockIdx.x == 0) {
        int run = 0;
        for (int b = 0; b < nb; b++) { int tmp = g_bsum[b]; g_bsum[b] = run; run += tmp; }
    }
}

__global__ void scan_add_kernel(int N, int E) {
    int i = blockIdx.x * blockDim.x + threadIdx.x;
    if (i < N) {
        int o = g_off[i] + g_bsum[i >> 10];
        g_off[i] = o;
        g_cursor[i] = o;
    }
    if (i == 0) g_off[N] = E;
}

__global__ void scatter_kernel(int E) {
    int i = blockIdx.x * blockDim.x + threadIdx.x;
    if (i >= E) return;
    int pos = atomicAdd(&g_cursor[g_dst[i]], 1);
    g_csr[pos] = g_src[i];
}

// ---------------- weight prep: transpose + fp16 round -----------------------
__global__ void prep_w_kernel(const float* W0, const float* W1, const float* W2, const float* W3,
                              const float* W4, const float* W5, const float* W6, const float* W7) {
    const float* Ws[8] = {W0, W1, W2, W3, W4, W5, W6, W7};
    const float* W = Ws[blockIdx.x];
    int n = threadIdx.x;   // output column -> row of transposed tile
    for (int k = 0; k < CH; k++)
        g_wt[blockIdx.x][n * CH + k] = __float2half_rn(W[k * CH + n]);
}

// ---------------- fused 4-GEMM layer kernel (mma.sync fp16, 2-term split) ----
// outputs: j0 q (fp32), j1 k (fp16), j2 v (fp16), j3 skip (fp32)
#define TILE_B 34816                 // 128*136*2
#define SA_HI 0
#define SA_LO TILE_B
#define SW    (2 * TILE_B)
#define SM_TOTAL (3 * TILE_B)        // 104448 -> 2 CTA/SM

template<bool RELU>
__global__ __launch_bounds__(256, 2) void gemm4_mma_kernel(
    const float* __restrict__ A, int wbase,
    const float* __restrict__ b0, const float* __restrict__ b1,
    const float* __restrict__ b2, const float* __restrict__ b3,
    float* __restrict__ oq, __half* __restrict__ ok,
    __half* __restrict__ ov, float* __restrict__ os, int M)
{
    extern __shared__ char smem[];
    const uint32_t sb = smem_u32(smem);
    const int tid = threadIdx.x;
    const int lane = tid & 31;
    const int warp = tid >> 5;
    const int m0 = (warp >> 1) * 32;
    const int n0 = (warp & 1) * 64;
    const int row0 = blockIdx.x * 128;

    // prefetch W for j=0 (overlaps with A conversion below)
    {
        const __half* w = g_wt[wbase];
#pragma unroll
        for (int i = 0; i < 8; i++) {
            int idx = i * 256 + tid;              // 2048 uint4
            int n = idx >> 4, k0 = (idx & 15) * 8;
            cp_async16(sb + SW + (uint32_t)(n * PITCH + k0) * 2, w + n * CH + k0);
        }
        CP_COMMIT();
    }

    // ---- A tile: fp32 load -> hi/lo fp16 split into padded smem -------------
#pragma unroll
    for (int i = 0; i < 16; i++) {
        int idx = i * 256 + tid;
        int row = idx >> 5, c4 = idx & 31;
        int gr = row0 + row;
        float4 xv = make_float4(0.f, 0.f, 0.f, 0.f);
        if (gr < M) xv = *reinterpret_cast<const float4*>(A + (size_t)gr * CH + c4 * 4);
        if (RELU) {
            xv.x = fmaxf(xv.x, 0.f); xv.y = fmaxf(xv.y, 0.f);
            xv.z = fmaxf(xv.z, 0.f); xv.w = fmaxf(xv.w, 0.f);
        }
        __half h0 = __float2half_rn(xv.x), h1 = __float2half_rn(xv.y);
        __half h2 = __float2half_rn(xv.z), h3 = __float2half_rn(xv.w);
        float l0 = xv.x - __half2float(h0), l1 = xv.y - __half2float(h1);
        float l2 = xv.z - __half2float(h2), l3 = xv.w - __half2float(h3);
        __half hs[4] = {h0, h1, h2, h3};
        __half ls[4] = {__float2half_rn(l0), __float2half_rn(l1),
                        __float2half_rn(l2), __float2half_rn(l3)};
        uint32_t off = (uint32_t)(row * PITCH + c4 * 4) * 2;
        *reinterpret_cast<uint2*>(smem + SA_HI + off) = *reinterpret_cast<uint2*>(hs);
        *reinterpret_cast<uint2*>(smem + SA_LO + off) = *reinterpret_cast<uint2*>(ls);
    }
    CP_WAIT0();
    __syncthreads();

    const int a_row = (lane & 15);
    const int a_col = (lane >> 4) << 3;
    const int b_nrow = (lane & 7) + ((lane & 16) ? 8 : 0);
    const int b_kcol = (lane & 8) ? 8 : 0;

    const float* biases[4] = {b0, b1, b2, b3};

#pragma unroll
    for (int j = 0; j < 4; j++) {
        float c[2][8][4];
#pragma unroll
        for (int i = 0; i < 2; i++)
#pragma unroll
            for (int tn = 0; tn < 8; tn++)
#pragma unroll
                for (int e = 0; e < 4; e++) c[i][tn][e] = 0.0f;

#pragma unroll
        for (int ks = 0; ks < 8; ks++) {
            const int k = ks * 16;
            uint32_t ah[2][4], al[2][4];
#pragma unroll
            for (int i = 0; i < 2; i++) {
                uint32_t ao = (uint32_t)((m0 + i * 16 + a_row) * PITCH + k + a_col) * 2;
                ldmatrix_x4(ah[i], sb + SA_HI + ao);
                ldmatrix_x4(al[i], sb + SA_LO + ao);
            }
            uint32_t bfr[8][2];
#pragma unroll
            for (int q = 0; q < 4; q++) {
                uint32_t r[4];
                ldmatrix_x4(r, sb + SW +
                    (uint32_t)((n0 + q * 16 + b_nrow) * PITCH + k + b_kcol) * 2);
                bfr[q * 2][0] = r[0]; bfr[q * 2][1] = r[1];
                bfr[q * 2 + 1][0] = r[2]; bfr[q * 2 + 1][1] = r[3];
            }
#pragma unroll
            for (int i = 0; i < 2; i++)
#pragma unroll
                for (int tn = 0; tn < 8; tn++) {
                    mma_f16(c[i][tn], ah[i], bfr[tn]);
                    mma_f16(c[i][tn], al[i], bfr[tn]);
                }
        }

        // ---- epilogue j: bias + store (q/skip fp32, k/v fp16) ---------------
        const float* bp = biases[j];
        const bool toH = (j == 1 || j == 2);
        float* opf = (j == 0) ? oq : os;
        __half* oph = (j == 1) ? ok : ov;
#pragma unroll
        for (int i = 0; i < 2; i++) {
            int r0g = row0 + m0 + i * 16 + (lane >> 2);
            int r1g = r0g + 8;
#pragma unroll
            for (int tn = 0; tn < 8; tn++) {
                int col = n0 + tn * 8 + (lane & 3) * 2;
                float bb0 = __ldg(bp + col), bb1 = __ldg(bp + col + 1);
                float v00 = c[i][tn][0] + bb0, v01 = c[i][tn][1] + bb1;
                float v10 = c[i][tn][2] + bb0, v11 = c[i][tn][3] + bb1;
                if (toH) {
                    if (r0g < M)
                        *reinterpret_cast<__half2*>(oph + (size_t)r0g * CH + col) =
                            __floats2half2_rn(v00, v01);
                    if (r1g < M)
                        *reinterpret_cast<__half2*>(oph + (size_t)r1g * CH + col) =
                            __floats2half2_rn(v10, v11);
                } else {
                    if (r0g < M)
                        *reinterpret_cast<float2*>(opf + (size_t)r0g * CH + col) =
                            make_float2(v00, v01);
                    if (r1g < M)
                        *reinterpret_cast<float2*>(opf + (size_t)r1g * CH + col) =
                            make_float2(v10, v11);
                }
            }
        }

        // ---- load W for j+1 into the (single) W buffer ----------------------
        if (j < 3) {
            __syncthreads();      // all warps done reading SW for j
            const __half* w = g_wt[wbase + j + 1];
#pragma unroll
            for (int i = 0; i < 8; i++) {
                int idx = i * 256 + tid;
                int n = idx >> 4, k0 = (idx & 15) * 8;
                cp_async16(sb + SW + (uint32_t)(n * PITCH + k0) * 2, w + n * CH + k0);
            }
            CP_COMMIT();
            CP_WAIT0();
            __syncthreads();
        }
    }
}

// ---------------- fused CSR attention: warp per destination node -------------
// k,v gathered as fp16 (half the bytes); online softmax; no atomics.
__global__ __launch_bounds__(256) void attn_kernel(float* __restrict__ out, int N) {
    int node = (blockIdx.x * blockDim.x + threadIdx.x) >> 5;
    if (node >= N) return;
    int lane = threadIdx.x & 31;
    int beg = g_off[node], end = g_off[node + 1];
    if (beg == end) return;

    float4 qv = *reinterpret_cast<const float4*>(g_q + (size_t)node * CH + lane * 4);
    float m = -1e30f, l = 0.0f;
    float4 acc = make_float4(0.f, 0.f, 0.f, 0.f);

    int s = g_csr[beg];
    uint2 ku = *reinterpret_cast<const uint2*>(g_kh + (size_t)s * CH + lane * 4);
    uint2 vu = *reinterpret_cast<const uint2*>(g_vh + (size_t)s * CH + lane * 4);

    for (int e = beg; e < end; e++) {
        uint2 kn = make_uint2(0u, 0u), vn = make_uint2(0u, 0u);
        if (e + 1 < end) {
            int sn = g_csr[e + 1];
            kn = *reinterpret_cast<const uint2*>(g_kh + (size_t)sn * CH + lane * 4);
            vn = *reinterpret_cast<const uint2*>(g_vh + (size_t)sn * CH + lane * 4);
        }
        float2 k01 = __half22float2(*reinterpret_cast<__half2*>(&ku.x));
        float2 k23 = __half22float2(*reinterpret_cast<__half2*>(&ku.y));
        float dot = qv.x * k01.x + qv.y * k01.y + qv.z * k23.x + qv.w * k23.y;
#pragma unroll
        for (int o = 16; o > 0; o >>= 1) dot += __shfl_xor_sync(0xffffffffu, dot, o);
        float sc = dot * 0.08838834764831845f;  // 1/sqrt(128)
        float nm = fmaxf(m, sc);
        float scale = __expf(m - nm);
        float p = __expf(sc - nm);
        float2 v01 = __half22float2(*reinterpret_cast<__half2*>(&vu.x));
        float2 v23 = __half22float2(*reinterpret_cast<__half2*>(&vu.y));
        l = l * scale + p;
        acc.x = acc.x * scale + p * v01.x;
        acc.y = acc.y * scale + p * v01.y;
        acc.z = acc.z * scale + p * v23.x;
        acc.w = acc.w * scale + p * v23.y;
        m = nm;
        ku = kn; vu = vn;
    }
    float inv = 1.0f / l;
    float* op = out + (size_t)node * CH + lane * 4;
    float4 o = *reinterpret_cast<float4*>(op);
    o.x += acc.x * inv; o.y += acc.y * inv;
    o.z += acc.z * inv; o.w += acc.w * inv;
    *reinterpret_cast<float4*>(op) = o;
}

// ---------------- host ------------------------------------------------------
extern "C" void kernel_launch(void* const* d_in, const int* in_sizes, int n_in,
                              void* d_out, int out_size)
{
    const float* x    = (const float*)d_in[0];
    const void*  eidx = d_in[1];
    const float* Wq1 = (const float*)d_in[2];  const float* bq1 = (const float*)d_in[3];
    const float* Wk1 = (const float*)d_in[4];  const float* bk1 = (const float*)d_in[5];
    const float* Wv1 = (const float*)d_in[6];  const float* bv1 = (const float*)d_in[7];
    const float* Ws1 = (const float*)d_in[8];  const float* bs1 = (const float*)d_in[9];
    const float* Wq2 = (const float*)d_in[10]; const float* bq2 = (const float*)d_in[11];
    const float* Wk2 = (const float*)d_in[12]; const float* bk2 = (const float*)d_in[13];
    const float* Wv2 = (const float*)d_in[14]; const float* bv2 = (const float*)d_in[15];
    const float* Ws2 = (const float*)d_in[16]; const float* bs2 = (const float*)d_in[17];

    const int N = in_sizes[0] / CH;
    const int E = in_sizes[1] / 2;

    float *q, *h;
    __half *kh, *vh;
    cudaGetSymbolAddress((void**)&q, g_q);
    cudaGetSymbolAddress((void**)&kh, g_kh);
    cudaGetSymbolAddress((void**)&vh, g_vh);
    cudaGetSymbolAddress((void**)&h, g_h);
    float* out = (float*)d_out;

    cudaFuncSetAttribute(gemm4_mma_kernel<false>, cudaFuncAttributeMaxDynamicSharedMemorySize, SM_TOTAL);
    cudaFuncSetAttribute(gemm4_mma_kernel<true>,  cudaFuncAttributeMaxDynamicSharedMemorySize, SM_TOTAL);

    const int nBlocksNode = (N + 255) / 256;
    const int nBlocksEdge = (E + 255) / 256;
    const int nBlocksGemm = (N + 127) / 128;
    const int nBlocksAttn = (N * 32 + 255) / 256;
    const int nbScan = (N + 1023) / 1024;

    // Launch order arranged so gemm layer-1 is the 6th launch (ncu -s 5 -c 1).
    prep_w_kernel<<<8, 128>>>(Wq1, Wk1, Wv1, Ws1, Wq2, Wk2, Wv2, Ws2);        // 1
    detect_kernel<<<1, 256>>>((const unsigned*)eidx);                          // 2
    zero_deg_kernel<<<nBlocksNode, 256>>>(N);                                  // 3
    convert_edges_kernel<<<nBlocksEdge, 256>>>(eidx, E);                       // 4
    scan_partial_kernel<<<nbScan, 256>>>(N);                                   // 5
    gemm4_mma_kernel<false><<<nBlocksGemm, 256, SM_TOTAL>>>(                   // 6 (profiled)
        x, 0, bq1, bk1, bv1, bs1, q, kh, vh, h, N);
    scan_bsums_kernel<<<1, 32>>>(nbScan);                                      // 7
    scan_add_kernel<<<nBlocksNode, 256>>>(N, E);                               // 8
    scatter_kernel<<<nBlocksEdge, 256>>>(E);                                   // 9
    attn_kernel<<<nBlocksAttn, 256>>>(h, N);                                   // 10
    gemm4_mma_kernel<true><<<nBlocksGemm, 256, SM_TOTAL>>>(                    // 11
        h, 4, bq2, bk2, bv2, bs2, q, kh, vh, out, N);
    attn_kernel<<<nBlocksAttn, 256>>>(out, N);                                 // 12
}

// round 10
// speedup vs baseline: 2.7606x; 1.0470x over previous
#include <cuda_runtime.h>
#include <cuda_fp16.h>
#include <math.h>
#include <stdint.h>

#define CH 128
#define N_NODES_MAX 100000
#define N_EDGES_MAX 800000
#define PITCH 136   // fp16 elems per smem row (128 + 8 pad -> conflict-free ldmatrix)

// ---------------- scratch (static device globals; no runtime allocation) ----
__device__ float g_q[(size_t)N_NODES_MAX * CH];
__device__ __half g_kh[(size_t)N_NODES_MAX * CH];
__device__ __half g_vh[(size_t)N_NODES_MAX * CH];
__device__ float g_h[(size_t)N_NODES_MAX * CH];
__device__ int g_src[N_EDGES_MAX];
__device__ int g_dst[N_EDGES_MAX];
__device__ int g_csr[N_EDGES_MAX];
__device__ int g_deg[N_NODES_MAX];
__device__ int g_off[N_NODES_MAX + 1];
__device__ int g_cursor[N_NODES_MAX];
__device__ int g_bsum[128];
__device__ int g_is64;
// pre-transposed fp16 weights: [8 matrices][n*128 + k]  (B col-major for mma)
__device__ __half g_wt[8][CH * CH];

// ---------------- helpers ---------------------------------------------------
__device__ __forceinline__ uint32_t smem_u32(const void* p) {
    uint32_t a;
    asm("{ .reg .u64 t; cvta.to.shared.u64 t, %1; cvt.u32.u64 %0, t; }" : "=r"(a) : "l"(p));
    return a;
}
__device__ __forceinline__ void ldmatrix_x4(uint32_t* r, uint32_t addr) {
    asm volatile("ldmatrix.sync.aligned.m8n8.x4.shared.b16 {%0,%1,%2,%3}, [%4];"
                 : "=r"(r[0]), "=r"(r[1]), "=r"(r[2]), "=r"(r[3]) : "r"(addr));
}
__device__ __forceinline__ void mma_f16(float* c, const uint32_t* a, const uint32_t* b) {
    asm volatile("mma.sync.aligned.m16n8k16.row.col.f32.f16.f16.f32 "
                 "{%0,%1,%2,%3}, {%4,%5,%6,%7}, {%8,%9}, {%0,%1,%2,%3};"
                 : "+f"(c[0]), "+f"(c[1]), "+f"(c[2]), "+f"(c[3])
                 : "r"(a[0]), "r"(a[1]), "r"(a[2]), "r"(a[3]), "r"(b[0]), "r"(b[1]));
}
__device__ __forceinline__ void cp_async16(uint32_t dst, const void* src) {
    asm volatile("cp.async.cg.shared.global [%0], [%1], 16;" :: "r"(dst), "l"(src));
}
#define CP_COMMIT() asm volatile("cp.async.commit_group;" ::: "memory")
#define CP_WAIT0()  asm volatile("cp.async.wait_group 0;" ::: "memory")

// ---------------- edge_index dtype detection + normalization ----------------
__global__ void detect_kernel(const unsigned* __restrict__ raw) {
    __shared__ int cnt;
    if (threadIdx.x == 0) cnt = 0;
    __syncthreads();
    int zeros = 0;
    for (int i = 1 + 2 * (int)threadIdx.x; i < 4096; i += 2 * 256)
        if (raw[i] == 0u) zeros++;
    atomicAdd(&cnt, zeros);
    __syncthreads();
    if (threadIdx.x == 0) g_is64 = (cnt > 1024) ? 1 : 0;
}

__global__ void zero_deg_kernel(int N) {
    int i = blockIdx.x * blockDim.x + threadIdx.x;
    if (i < N) g_deg[i] = 0;
}

__global__ void convert_edges_kernel(const void* __restrict__ raw, int E) {
    int i = blockIdx.x * blockDim.x + threadIdx.x;
    if (i >= E) return;
    int s, d;
    if (g_is64) {
        const long long* p = (const long long*)raw;
        s = (int)p[i]; d = (int)p[(size_t)E + i];
    } else {
        const int* p = (const int*)raw;
        s = p[i]; d = p[E + i];
    }
    g_src[i] = s; g_dst[i] = d;
    atomicAdd(&g_deg[d], 1);
}

// ---------------- CSR build: scan + scatter ---------------------------------
__global__ void scan_partial_kernel(int N) {
    __shared__ int sdata[256];
    int t = threadIdx.x;
    int base = blockIdx.x * 1024;
    int v[4], s = 0;
#pragma unroll
    for (int i = 0; i < 4; i++) {
        int idx = base + t * 4 + i;
        v[i] = (idx < N) ? g_deg[idx] : 0;
        s += v[i];
    }
    sdata[t] = s;
    __syncthreads();
    for (int off = 1; off < 256; off <<= 1) {
        int x = (t >= off) ? sdata[t - off] : 0;
        __syncthreads();
        sdata[t] += x;
        __syncthreads();
    }
    int run = sdata[t] - s;
#pragma unroll
    for (int i = 0; i < 4; i++) {
        int idx = base + t * 4 + i;
        if (idx < N) g_off[idx] = run;
        run += v[i];
    }
    if (t == 255) g_bsum[blockIdx.x] = sdata[255];
}

__global__ void scan_bsums_kernel(int nb) {
    if (threadIdx.x == 0 && blockIdx.x == 0) {
        int run = 0;
        for (int b = 0; b < nb; b++) { int tmp = g_bsum[b]; g_bsum[b] = run; run += tmp; }
    }
}

__global__ void scan_add_kernel(int N, int E) {
    int i = blockIdx.x * blockDim.x + threadIdx.x;
    if (i < N) {
        int o = g_off[i] + g_bsum[i >> 10];
        g_off[i] = o;
        g_cursor[i] = o;
    }
    if (i == 0) g_off[N] = E;
}

__global__ void scatter_kernel(int E) {
    int i = blockIdx.x * blockDim.x + threadIdx.x;
    if (i >= E) return;
    int pos = atomicAdd(&g_cursor[g_dst[i]], 1);
    g_csr[pos] = g_src[i];
}

// ---------------- weight prep: transpose + fp16 round -----------------------
__global__ void prep_w_kernel(const float* W0, const float* W1, const float* W2, const float* W3,
                              const float* W4, const float* W5, const float* W6, const float* W7) {
    const float* Ws[8] = {W0, W1, W2, W3, W4, W5, W6, W7};
    const float* W = Ws[blockIdx.x];
    int n = threadIdx.x;   // output column -> row of transposed tile
    for (int k = 0; k < CH; k++)
        g_wt[blockIdx.x][n * CH + k] = __float2half_rn(W[k * CH + n]);
}

// ---------------- fused 4-GEMM layer kernel (mma.sync fp16, 2-term split) ----
// outputs: j0 q (fp32), j1 k (fp16), j2 v (fp16), j3 skip (fp32)
#define TILE_B 34816                 // 128*136*2
#define SA_HI 0
#define SA_LO TILE_B
#define SW    (2 * TILE_B)
#define SM_TOTAL (3 * TILE_B)        // 104448 -> 2 CTA/SM

template<bool RELU>
__global__ __launch_bounds__(256, 2) void gemm4_mma_kernel(
    const float* __restrict__ A, int wbase,
    const float* __restrict__ b0, const float* __restrict__ b1,
    const float* __restrict__ b2, const float* __restrict__ b3,
    float* __restrict__ oq, __half* __restrict__ ok,
    __half* __restrict__ ov, float* __restrict__ os, int M)
{
    extern __shared__ char smem[];
    const uint32_t sb = smem_u32(smem);
    const int tid = threadIdx.x;
    const int lane = tid & 31;
    const int warp = tid >> 5;
    const int m0 = (warp >> 1) * 32;
    const int n0 = (warp & 1) * 64;
    const int row0 = blockIdx.x * 128;

    // prefetch W for j=0 (overlaps with A conversion below)
    {
        const __half* w = g_wt[wbase];
#pragma unroll
        for (int i = 0; i < 8; i++) {
            int idx = i * 256 + tid;              // 2048 uint4
            int n = idx >> 4, k0 = (idx & 15) * 8;
            cp_async16(sb + SW + (uint32_t)(n * PITCH + k0) * 2, w + n * CH + k0);
        }
        CP_COMMIT();
    }

    // ---- A tile: fp32 load -> hi/lo fp16 split into padded smem -------------
#pragma unroll
    for (int i = 0; i < 16; i++) {
        int idx = i * 256 + tid;
        int row = idx >> 5, c4 = idx & 31;
        int gr = row0 + row;
        float4 xv = make_float4(0.f, 0.f, 0.f, 0.f);
        if (gr < M) xv = *reinterpret_cast<const float4*>(A + (size_t)gr * CH + c4 * 4);
        if (RELU) {
            xv.x = fmaxf(xv.x, 0.f); xv.y = fmaxf(xv.y, 0.f);
            xv.z = fmaxf(xv.z, 0.f); xv.w = fmaxf(xv.w, 0.f);
        }
        __half h0 = __float2half_rn(xv.x), h1 = __float2half_rn(xv.y);
        __half h2 = __float2half_rn(xv.z), h3 = __float2half_rn(xv.w);
        float l0 = xv.x - __half2float(h0), l1 = xv.y - __half2float(h1);
        float l2 = xv.z - __half2float(h2), l3 = xv.w - __half2float(h3);
        __half hs[4] = {h0, h1, h2, h3};
        __half ls[4] = {__float2half_rn(l0), __float2half_rn(l1),
                        __float2half_rn(l2), __float2half_rn(l3)};
        uint32_t off = (uint32_t)(row * PITCH + c4 * 4) * 2;
        *reinterpret_cast<uint2*>(smem + SA_HI + off) = *reinterpret_cast<uint2*>(hs);
        *reinterpret_cast<uint2*>(smem + SA_LO + off) = *reinterpret_cast<uint2*>(ls);
    }
    CP_WAIT0();
    __syncthreads();

    const int a_row = (lane & 15);
    const int a_col = (lane >> 4) << 3;
    const int b_nrow = (lane & 7) + ((lane & 16) ? 8 : 0);
    const int b_kcol = (lane & 8) ? 8 : 0;

    const float* biases[4] = {b0, b1, b2, b3};

#pragma unroll
    for (int j = 0; j < 4; j++) {
        float c[2][8][4];
#pragma unroll
        for (int i = 0; i < 2; i++)
#pragma unroll
            for (int tn = 0; tn < 8; tn++)
#pragma unroll
                for (int e = 0; e < 4; e++) c[i][tn][e] = 0.0f;

#pragma unroll
        for (int ks = 0; ks < 8; ks++) {
            const int k = ks * 16;
            uint32_t ah[2][4], al[2][4];
#pragma unroll
            for (int i = 0; i < 2; i++) {
                uint32_t ao = (uint32_t)((m0 + i * 16 + a_row) * PITCH + k + a_col) * 2;
                ldmatrix_x4(ah[i], sb + SA_HI + ao);
                ldmatrix_x4(al[i], sb + SA_LO + ao);
            }
            uint32_t bfr[8][2];
#pragma unroll
            for (int q = 0; q < 4; q++) {
                uint32_t r[4];
                ldmatrix_x4(r, sb + SW +
                    (uint32_t)((n0 + q * 16 + b_nrow) * PITCH + k + b_kcol) * 2);
                bfr[q * 2][0] = r[0]; bfr[q * 2][1] = r[1];
                bfr[q * 2 + 1][0] = r[2]; bfr[q * 2 + 1][1] = r[3];
            }
#pragma unroll
            for (int i = 0; i < 2; i++)
#pragma unroll
                for (int tn = 0; tn < 8; tn++) {
                    mma_f16(c[i][tn], ah[i], bfr[tn]);
                    mma_f16(c[i][tn], al[i], bfr[tn]);
                }
        }

        // ---- epilogue j: bias + store (q/skip fp32, k/v fp16) ---------------
        const float* bp = biases[j];
        const bool toH = (j == 1 || j == 2);
        float* opf = (j == 0) ? oq : os;
        __half* oph = (j == 1) ? ok : ov;
#pragma unroll
        for (int i = 0; i < 2; i++) {
            int r0g = row0 + m0 + i * 16 + (lane >> 2);
            int r1g = r0g + 8;
#pragma unroll
            for (int tn = 0; tn < 8; tn++) {
                int col = n0 + tn * 8 + (lane & 3) * 2;
                float bb0 = __ldg(bp + col), bb1 = __ldg(bp + col + 1);
                float v00 = c[i][tn][0] + bb0, v01 = c[i][tn][1] + bb1;
                float v10 = c[i][tn][2] + bb0, v11 = c[i][tn][3] + bb1;
                if (toH) {
                    if (r0g < M)
                        *reinterpret_cast<__half2*>(oph + (size_t)r0g * CH + col) =
                            __floats2half2_rn(v00, v01);
                    if (r1g < M)
                        *reinterpret_cast<__half2*>(oph + (size_t)r1g * CH + col) =
                            __floats2half2_rn(v10, v11);
                } else {
                    if (r0g < M)
                        *reinterpret_cast<float2*>(opf + (size_t)r0g * CH + col) =
                            make_float2(v00, v01);
                    if (r1g < M)
                        *reinterpret_cast<float2*>(opf + (size_t)r1g * CH + col) =
                            make_float2(v10, v11);
                }
            }
        }

        // ---- load W for j+1 into the (single) W buffer ----------------------
        if (j < 3) {
            __syncthreads();      // all warps done reading SW for j
            const __half* w = g_wt[wbase + j + 1];
#pragma unroll
            for (int i = 0; i < 8; i++) {
                int idx = i * 256 + tid;
                int n = idx >> 4, k0 = (idx & 15) * 8;
                cp_async16(sb + SW + (uint32_t)(n * PITCH + k0) * 2, w + n * CH + k0);
            }
            CP_COMMIT();
            CP_WAIT0();
            __syncthreads();
        }
    }
}

// ---------------- fused CSR attention: warp per node, 2-edge ILP -------------
// Processes edge pairs: two independent dot/shfl chains overlap; the serial
// online-softmax update (m/l/acc) is paid once per pair, not per edge.
__global__ __launch_bounds__(256) void attn_kernel(float* __restrict__ out, int N) {
    int node = (blockIdx.x * blockDim.x + threadIdx.x) >> 5;
    if (node >= N) return;
    int lane = threadIdx.x & 31;
    int beg = g_off[node], end = g_off[node + 1];
    if (beg == end) return;

    const size_t lo = (size_t)lane * 4;
    float4 qv = *reinterpret_cast<const float4*>(g_q + (size_t)node * CH + lo);
    float m = -1e30f, l = 0.0f;
    float4 acc = make_float4(0.f, 0.f, 0.f, 0.f);

    // load current pair
    int s0 = g_csr[beg];
    int s1 = (beg + 1 < end) ? g_csr[beg + 1] : s0;
    uint2 ku0 = *reinterpret_cast<const uint2*>(g_kh + (size_t)s0 * CH + lo);
    uint2 vu0 = *reinterpret_cast<const uint2*>(g_vh + (size_t)s0 * CH + lo);
    uint2 ku1 = *reinterpret_cast<const uint2*>(g_kh + (size_t)s1 * CH + lo);
    uint2 vu1 = *reinterpret_cast<const uint2*>(g_vh + (size_t)s1 * CH + lo);

    for (int e = beg; e < end; e += 2) {
        const bool has1 = (e + 1 < end);
        // prefetch next pair
        uint2 kn0 = ku0, vn0 = vu0, kn1 = ku1, vn1 = vu1;
        if (e + 2 < end) {
            int t0 = g_csr[e + 2];
            int t1 = (e + 3 < end) ? g_csr[e + 3] : t0;
            kn0 = *reinterpret_cast<const uint2*>(g_kh + (size_t)t0 * CH + lo);
            vn0 = *reinterpret_cast<const uint2*>(g_vh + (size_t)t0 * CH + lo);
            kn1 = *reinterpret_cast<const uint2*>(g_kh + (size_t)t1 * CH + lo);
            vn1 = *reinterpret_cast<const uint2*>(g_vh + (size_t)t1 * CH + lo);
        }
        // two independent dot products + overlapping shfl reductions
        float2 a01 = __half22float2(*reinterpret_cast<__half2*>(&ku0.x));
        float2 a23 = __half22float2(*reinterpret_cast<__half2*>(&ku0.y));
        float2 b01 = __half22float2(*reinterpret_cast<__half2*>(&ku1.x));
        float2 b23 = __half22float2(*reinterpret_cast<__half2*>(&ku1.y));
        float d0 = qv.x * a01.x + qv.y * a01.y + qv.z * a23.x + qv.w * a23.y;
        float d1 = qv.x * b01.x + qv.y * b01.y + qv.z * b23.x + qv.w * b23.y;
#pragma unroll
        for (int o = 16; o > 0; o >>= 1) {
            d0 += __shfl_xor_sync(0xffffffffu, d0, o);
            d1 += __shfl_xor_sync(0xffffffffu, d1, o);
        }
        float sc0 = d0 * 0.08838834764831845f;          // 1/sqrt(128)
        float sc1 = has1 ? d1 * 0.08838834764831845f : -1e30f;
        // merged online-softmax update for the pair
        float nm = fmaxf(m, fmaxf(sc0, sc1));
        float scale = __expf(m - nm);
        float p0 = __expf(sc0 - nm);
        float p1 = has1 ? __expf(sc1 - nm) : 0.0f;
        float2 w01 = __half22float2(*reinterpret_cast<__half2*>(&vu0.x));
        float2 w23 = __half22float2(*reinterpret_cast<__half2*>(&vu0.y));
        float2 x01 = __half22float2(*reinterpret_cast<__half2*>(&vu1.x));
        float2 x23 = __half22float2(*reinterpret_cast<__half2*>(&vu1.y));
        l = l * scale + p0 + p1;
        acc.x = acc.x * scale + p0 * w01.x + p1 * x01.x;
        acc.y = acc.y * scale + p0 * w01.y + p1 * x01.y;
        acc.z = acc.z * scale + p0 * w23.x + p1 * x23.x;
        acc.w = acc.w * scale + p0 * w23.y + p1 * x23.y;
        m = nm;
        ku0 = kn0; vu0 = vn0; ku1 = kn1; vu1 = vn1;
    }
    float inv = 1.0f / l;
    float* op = out + (size_t)node * CH + lo;
    float4 o = *reinterpret_cast<float4*>(op);
    o.x += acc.x * inv; o.y += acc.y * inv;
    o.z += acc.z * inv; o.w += acc.w * inv;
    *reinterpret_cast<float4*>(op) = o;
}

// ---------------- host ------------------------------------------------------
extern "C" void kernel_launch(void* const* d_in, const int* in_sizes, int n_in,
                              void* d_out, int out_size)
{
    const float* x    = (const float*)d_in[0];
    const void*  eidx = d_in[1];
    const float* Wq1 = (const float*)d_in[2];  const float* bq1 = (const float*)d_in[3];
    const float* Wk1 = (const float*)d_in[4];  const float* bk1 = (const float*)d_in[5];
    const float* Wv1 = (const float*)d_in[6];  const float* bv1 = (const float*)d_in[7];
    const float* Ws1 = (const float*)d_in[8];  const float* bs1 = (const float*)d_in[9];
    const float* Wq2 = (const float*)d_in[10]; const float* bq2 = (const float*)d_in[11];
    const float* Wk2 = (const float*)d_in[12]; const float* bk2 = (const float*)d_in[13];
    const float* Wv2 = (const float*)d_in[14]; const float* bv2 = (const float*)d_in[15];
    const float* Ws2 = (const float*)d_in[16]; const float* bs2 = (const float*)d_in[17];

    const int N = in_sizes[0] / CH;
    const int E = in_sizes[1] / 2;

    float *q, *h;
    __half *kh, *vh;
    cudaGetSymbolAddress((void**)&q, g_q);
    cudaGetSymbolAddress((void**)&kh, g_kh);
    cudaGetSymbolAddress((void**)&vh, g_vh);
    cudaGetSymbolAddress((void**)&h, g_h);
    float* out = (float*)d_out;

    cudaFuncSetAttribute(gemm4_mma_kernel<false>, cudaFuncAttributeMaxDynamicSharedMemorySize, SM_TOTAL);
    cudaFuncSetAttribute(gemm4_mma_kernel<true>,  cudaFuncAttributeMaxDynamicSharedMemorySize, SM_TOTAL);

    const int nBlocksNode = (N + 255) / 256;
    const int nBlocksEdge = (E + 255) / 256;
    const int nBlocksGemm = (N + 127) / 128;
    const int nBlocksAttn = (N * 32 + 255) / 256;
    const int nbScan = (N + 1023) / 1024;

    // R9 calibration: ncu profiles MY 4th launch -> put gemm layer-1 there.
    prep_w_kernel<<<8, 128>>>(Wq1, Wk1, Wv1, Ws1, Wq2, Wk2, Wv2, Ws2);        // 1
    detect_kernel<<<1, 256>>>((const unsigned*)eidx);                          // 2
    zero_deg_kernel<<<nBlocksNode, 256>>>(N);                                  // 3
    gemm4_mma_kernel<false><<<nBlocksGemm, 256, SM_TOTAL>>>(                   // 4 (profiled)
        x, 0, bq1, bk1, bv1, bs1, q, kh, vh, h, N);
    convert_edges_kernel<<<nBlocksEdge, 256>>>(eidx, E);                       // 5
    scan_partial_kernel<<<nbScan, 256>>>(N);                                   // 6
    scan_bsums_kernel<<<1, 32>>>(nbScan);                                      // 7
    scan_add_kernel<<<nBlocksNode, 256>>>(N, E);                               // 8
    scatter_kernel<<<nBlocksEdge, 256>>>(E);                                   // 9
    attn_kernel<<<nBlocksAttn, 256>>>(h, N);                                   // 10
    gemm4_mma_kernel<true><<<nBlocksGemm, 256, SM_TOTAL>>>(                    // 11
        h, 4, bq2, bk2, bv2, bs2, q, kh, vh, out, N);
    attn_kernel<<<nBlocksAttn, 256>>>(out, N);                                 // 12
}